// round 1
// baseline (speedup 1.0000x reference)
#include <cuda_runtime.h>
#include <math.h>
#include <math_constants.h>

#define BSZ 4
#define TQ 1024
#define EDIM 768
#define NH 12
#define HD 64
#define NB 320
#define MTOT (BSZ*TQ)   // 4096

// ---------------- scratch (static device globals; no allocation) ----------------
__device__ float g_weffq[EDIM*EDIM];
__device__ float g_weffk[EDIM*EDIM];
__device__ float g_weffv[EDIM*EDIM];
__device__ float g_q1[MTOT*EDIM];
__device__ float g_k1[MTOT*EDIM];
__device__ float g_v1[MTOT*EDIM];
__device__ float g_qq[MTOT*EDIM];
__device__ float g_kk[MTOT*EDIM];
__device__ float g_vv[MTOT*EDIM];
__device__ float g_ctx[MTOT*EDIM];
__device__ float g_gate[BSZ*NH*TQ];
__device__ int   g_bucket[TQ*TQ];

// ---------------- Weff = W + 0.5 * B @ A  (folds LoRA into the weight) ----------
__global__ void build_weff_kernel(const float* __restrict__ W,
                                  const float* __restrict__ A,   // [2, E]
                                  const float* __restrict__ Bm,  // [E, 2]
                                  float* __restrict__ out)
{
    int idx = blockIdx.x * blockDim.x + threadIdx.x;
    if (idx >= EDIM*EDIM) return;
    int o = idx / EDIM;
    int e = idx - o*EDIM;
    out[idx] = W[idx] + 0.5f * (Bm[o*2+0]*A[e] + Bm[o*2+1]*A[EDIM + e]);
}

// ---------------- SGEMM: C[m,n] = scale * (sum_k A[m,k]*W[n,k] + bias[n]) --------
// M,N multiples of 128; K multiple of 16. 256 threads, 128x128 tile, 8x8/thread.
#define GBM 128
#define GBN 128
#define GBK 16

__global__ __launch_bounds__(256) void sgemm_nt_kernel(
    const float* __restrict__ A, const float* __restrict__ W,
    const float* __restrict__ bias, float* __restrict__ C,
    int M, int N, int K, float scale)
{
    __shared__ float As[GBK][GBM];
    __shared__ float Ws[GBK][GBN];
    const int bm = blockIdx.y * GBM;
    const int bn = blockIdx.x * GBN;
    const int tid = threadIdx.x;
    const int tx = tid & 15;
    const int ty = tid >> 4;
    const int lr = tid >> 2;          // 0..63
    const int lc = (tid & 3) * 4;     // 0,4,8,12

    float acc[8][8];
#pragma unroll
    for (int i = 0; i < 8; i++)
#pragma unroll
        for (int j = 0; j < 8; j++) acc[i][j] = 0.f;

    for (int k0 = 0; k0 < K; k0 += GBK) {
#pragma unroll
        for (int p = 0; p < 2; p++) {
            int r = lr + p*64;
            float4 a4 = *(const float4*)(A + (size_t)(bm + r)*K + k0 + lc);
            As[lc+0][r] = a4.x; As[lc+1][r] = a4.y; As[lc+2][r] = a4.z; As[lc+3][r] = a4.w;
            float4 w4 = *(const float4*)(W + (size_t)(bn + r)*K + k0 + lc);
            Ws[lc+0][r] = w4.x; Ws[lc+1][r] = w4.y; Ws[lc+2][r] = w4.z; Ws[lc+3][r] = w4.w;
        }
        __syncthreads();
#pragma unroll
        for (int k = 0; k < GBK; k++) {
            float a[8], w[8];
#pragma unroll
            for (int i = 0; i < 4; i++) {
                a[i]   = As[k][ty*4 + i];
                a[4+i] = As[k][64 + ty*4 + i];
                w[i]   = Ws[k][tx*4 + i];
                w[4+i] = Ws[k][64 + tx*4 + i];
            }
#pragma unroll
            for (int i = 0; i < 8; i++)
#pragma unroll
                for (int j = 0; j < 8; j++)
                    acc[i][j] = fmaf(a[i], w[j], acc[i][j]);
        }
        __syncthreads();
    }
#pragma unroll
    for (int i = 0; i < 8; i++) {
        int row = bm + ((i < 4) ? (ty*4 + i) : (64 + ty*4 + (i-4)));
#pragma unroll
        for (int j = 0; j < 8; j++) {
            int col = bn + ((j < 4) ? (tx*4 + j) : (64 + tx*4 + (j-4)));
            C[(size_t)row*N + col] = scale * (acc[i][j] + bias[col]);
        }
    }
}

// ---------------- relative position bucket table [T,T] --------------------------
__global__ void bucket_kernel(int* __restrict__ bucket)
{
    int idx = blockIdx.x * blockDim.x + threadIdx.x;
    if (idx >= TQ*TQ) return;
    int i = idx / TQ;
    int j = idx - i*TQ;
    int rel = j - i;
    const int nb = NB/2;           // 160
    const int max_exact = nb/2;    // 80
    int b = (rel > 0) ? nb : 0;
    int r = abs(rel);
    if (r < max_exact) {
        b += r;
    } else {
        float log_ratio = logf((float)r / (float)max_exact);
        float denom = logf(800.0f / (float)max_exact);   // log(10) in fp32
        int large = max_exact + (int)(log_ratio / denom * (float)(nb - max_exact));
        if (large > nb - 1) large = nb - 1;
        b += large;
    }
    bucket[idx] = b;
}

// ---------------- gate[b,h,t] ----------------------------------------------------
__global__ void gate_kernel(const float* __restrict__ x,
                            const float* __restrict__ Wg,   // [8, HD]
                            const float* __restrict__ bg,   // [8]
                            const float* __restrict__ gru,  // [H] (shape 1,H,1,1)
                            float* __restrict__ gate)
{
    __shared__ float sWg[8*HD];
    __shared__ float sbg[8];
    int tid = threadIdx.x;
    for (int i = tid; i < 8*HD; i += blockDim.x) sWg[i] = Wg[i];
    if (tid < 8) sbg[tid] = bg[tid];
    __syncthreads();

    int idx = blockIdx.x * blockDim.x + tid;
    if (idx >= BSZ*NH*TQ) return;
    int t = idx % TQ;
    int h = (idx / TQ) % NH;
    int b = idx / (TQ*NH);

    const float* xp = x + ((size_t)b*TQ + t)*EDIM + h*HD;
    float gp[8];
#pragma unroll
    for (int e = 0; e < 8; e++) gp[e] = sbg[e];
#pragma unroll
    for (int d4 = 0; d4 < HD; d4 += 4) {
        float4 xv = *(const float4*)(xp + d4);
#pragma unroll
        for (int e = 0; e < 8; e++) {
            gp[e] = fmaf(xv.x, sWg[e*HD + d4+0], gp[e]);
            gp[e] = fmaf(xv.y, sWg[e*HD + d4+1], gp[e]);
            gp[e] = fmaf(xv.z, sWg[e*HD + d4+2], gp[e]);
            gp[e] = fmaf(xv.w, sWg[e*HD + d4+3], gp[e]);
        }
    }
    float s0 = gp[0]+gp[1]+gp[2]+gp[3];
    float s1 = gp[4]+gp[5]+gp[6]+gp[7];
    float ga = 1.0f / (1.0f + __expf(-s0));
    float gb = 1.0f / (1.0f + __expf(-s1));
    gate[idx] = ga * (gb * gru[h] - 1.0f) + 2.0f;
}

// ---------------- flash attention with gated rel-pos bias -----------------------
#define BQT 64
#define BKT 64
#define SP  65   // padded smem row stride

__global__ __launch_bounds__(256) void attn_kernel(
    const float* __restrict__ q, const float* __restrict__ k, const float* __restrict__ v,
    const float* __restrict__ gate, const int* __restrict__ bucket,
    const float* __restrict__ rel_embed,  // [NB, H]
    float* __restrict__ ctx)
{
    extern __shared__ float smem[];
    float* Qs = smem;                    // 64*65
    float* Ks = Qs + BQT*SP;             // 64*65
    float* Vs = Ks + BKT*SP;             // 64*65
    float* Ps = Vs + BKT*SP;             // 64*65
    float* relc = Ps + BQT*SP;           // 320

    const int q0  = blockIdx.x * BQT;
    const int h   = blockIdx.y;
    const int b   = blockIdx.z;
    const int tid = threadIdx.x;
    const int tx  = tid & 15;
    const int ty  = tid >> 4;

    const size_t base = ((size_t)b*TQ)*EDIM + h*HD;

    for (int i = tid; i < NB; i += 256) relc[i] = rel_embed[(size_t)i*NH + h];

    // load Q tile [64 x 64]
#pragma unroll
    for (int p = 0; p < 4; p++) {
        int id = tid + p*256;
        int r = id >> 4;
        int c = (id & 15) * 4;
        float4 v4 = *(const float4*)(q + base + (size_t)(q0 + r)*EDIM + c);
        Qs[r*SP + c+0] = v4.x; Qs[r*SP + c+1] = v4.y; Qs[r*SP + c+2] = v4.z; Qs[r*SP + c+3] = v4.w;
    }

    float m[4], l[4], grow[4];
    float acc[4][4];
#pragma unroll
    for (int i = 0; i < 4; i++) {
        m[i] = -1e30f; l[i] = 0.f;
        grow[i] = gate[((size_t)b*NH + h)*TQ + q0 + ty*4 + i];
#pragma unroll
        for (int j = 0; j < 4; j++) acc[i][j] = 0.f;
    }

    for (int k0 = 0; k0 < TQ; k0 += BKT) {
        __syncthreads();   // protect Ks/Vs/Ps from previous iteration readers
#pragma unroll
        for (int p = 0; p < 4; p++) {
            int id = tid + p*256;
            int r = id >> 4;
            int c = (id & 15) * 4;
            float4 kv = *(const float4*)(k + base + (size_t)(k0 + r)*EDIM + c);
            Ks[r*SP + c+0] = kv.x; Ks[r*SP + c+1] = kv.y; Ks[r*SP + c+2] = kv.z; Ks[r*SP + c+3] = kv.w;
            float4 vv = *(const float4*)(v + base + (size_t)(k0 + r)*EDIM + c);
            Vs[r*SP + c+0] = vv.x; Vs[r*SP + c+1] = vv.y; Vs[r*SP + c+2] = vv.z; Vs[r*SP + c+3] = vv.w;
        }
        __syncthreads();

        // S = Q @ K^T  (4x4 fragment per thread)
        float s[4][4];
#pragma unroll
        for (int i = 0; i < 4; i++)
#pragma unroll
            for (int j = 0; j < 4; j++) s[i][j] = 0.f;
#pragma unroll 8
        for (int d = 0; d < HD; d++) {
            float qa[4], kb[4];
#pragma unroll
            for (int i = 0; i < 4; i++) qa[i] = Qs[(ty*4+i)*SP + d];
#pragma unroll
            for (int j = 0; j < 4; j++) kb[j] = Ks[(tx*4+j)*SP + d];
#pragma unroll
            for (int i = 0; i < 4; i++)
#pragma unroll
                for (int j = 0; j < 4; j++) s[i][j] = fmaf(qa[i], kb[j], s[i][j]);
        }

        // gated rel-pos bias
#pragma unroll
        for (int i = 0; i < 4; i++) {
            const int* brow = bucket + (size_t)(q0 + ty*4 + i)*TQ + k0;
#pragma unroll
            for (int j = 0; j < 4; j++)
                s[i][j] = fmaf(grow[i], relc[brow[tx*4 + j]], s[i][j]);
        }

        // online softmax per row (16 lanes of a half-warp own one row group)
#pragma unroll
        for (int i = 0; i < 4; i++) {
            float tm = fmaxf(fmaxf(s[i][0], s[i][1]), fmaxf(s[i][2], s[i][3]));
#pragma unroll
            for (int off = 1; off < 16; off <<= 1)
                tm = fmaxf(tm, __shfl_xor_sync(0xffffffffu, tm, off));
            float mn = fmaxf(m[i], tm);
            float corr = __expf(m[i] - mn);
            float psum = 0.f;
#pragma unroll
            for (int j = 0; j < 4; j++) {
                s[i][j] = __expf(s[i][j] - mn);
                psum += s[i][j];
            }
#pragma unroll
            for (int off = 1; off < 16; off <<= 1)
                psum += __shfl_xor_sync(0xffffffffu, psum, off);
            l[i] = l[i]*corr + psum;
            m[i] = mn;
#pragma unroll
            for (int j = 0; j < 4; j++) acc[i][j] *= corr;
        }

        // stage P
#pragma unroll
        for (int i = 0; i < 4; i++)
#pragma unroll
            for (int j = 0; j < 4; j++)
                Ps[(ty*4+i)*SP + tx*4+j] = s[i][j];
        __syncthreads();

        // ctx += P @ V
#pragma unroll 8
        for (int kc = 0; kc < BKT; kc++) {
            float pv[4], vv[4];
#pragma unroll
            for (int i = 0; i < 4; i++) pv[i] = Ps[(ty*4+i)*SP + kc];
#pragma unroll
            for (int j = 0; j < 4; j++) vv[j] = Vs[kc*SP + tx*4+j];
#pragma unroll
            for (int i = 0; i < 4; i++)
#pragma unroll
                for (int j = 0; j < 4; j++) acc[i][j] = fmaf(pv[i], vv[j], acc[i][j]);
        }
    }

#pragma unroll
    for (int i = 0; i < 4; i++) {
        float inv = 1.0f / l[i];
#pragma unroll
        for (int j = 0; j < 4; j++)
            ctx[base + (size_t)(q0 + ty*4 + i)*EDIM + tx*4 + j] = acc[i][j] * inv;
    }
}

// ---------------- launch ---------------------------------------------------------
extern "C" void kernel_launch(void* const* d_in, const int* in_sizes, int n_in,
                              void* d_out, int out_size)
{
    const float* x   = (const float*)d_in[0];
    const float* Wq  = (const float*)d_in[1];
    const float* bq  = (const float*)d_in[2];
    const float* Wk  = (const float*)d_in[3];
    const float* bk  = (const float*)d_in[4];
    const float* Wv  = (const float*)d_in[5];
    const float* bv  = (const float*)d_in[6];
    const float* Aq  = (const float*)d_in[7];
    const float* Bq  = (const float*)d_in[8];
    const float* Ak  = (const float*)d_in[9];
    const float* Bk  = (const float*)d_in[10];
    const float* Av  = (const float*)d_in[11];
    const float* Bv  = (const float*)d_in[12];
    const float* Wo  = (const float*)d_in[13];
    const float* bo  = (const float*)d_in[14];
    const float* Wg  = (const float*)d_in[15];
    const float* bg  = (const float*)d_in[16];
    const float* gru = (const float*)d_in[17];
    const float* rel = (const float*)d_in[18];
    float* out = (float*)d_out;

    float *weffq, *weffk, *weffv, *q1, *k1, *v1, *qq, *kk, *vv, *ctx, *gate;
    int* bucket;
    cudaGetSymbolAddress((void**)&weffq, g_weffq);
    cudaGetSymbolAddress((void**)&weffk, g_weffk);
    cudaGetSymbolAddress((void**)&weffv, g_weffv);
    cudaGetSymbolAddress((void**)&q1, g_q1);
    cudaGetSymbolAddress((void**)&k1, g_k1);
    cudaGetSymbolAddress((void**)&v1, g_v1);
    cudaGetSymbolAddress((void**)&qq, g_qq);
    cudaGetSymbolAddress((void**)&kk, g_kk);
    cudaGetSymbolAddress((void**)&vv, g_vv);
    cudaGetSymbolAddress((void**)&ctx, g_ctx);
    cudaGetSymbolAddress((void**)&gate, g_gate);
    cudaGetSymbolAddress((void**)&bucket, g_bucket);

    const int attn_smem = (4*BQT*SP + NB) * (int)sizeof(float);
    static_assert((4*BQT*SP + NB)*4 < 220*1024, "smem");
    cudaFuncSetAttribute(attn_kernel, cudaFuncAttributeMaxDynamicSharedMemorySize, attn_smem);

    const int nw = EDIM*EDIM;
    build_weff_kernel<<<(nw+255)/256, 256>>>(Wq, Aq, Bq, weffq);
    build_weff_kernel<<<(nw+255)/256, 256>>>(Wk, Ak, Bk, weffk);
    build_weff_kernel<<<(nw+255)/256, 256>>>(Wv, Av, Bv, weffv);

    dim3 gg(EDIM/GBN, MTOT/GBM);   // (6, 32)
    sgemm_nt_kernel<<<gg, 256>>>(x,  weffq, bq, q1, MTOT, EDIM, EDIM, 1.0f);
    sgemm_nt_kernel<<<gg, 256>>>(x,  weffk, bk, k1, MTOT, EDIM, EDIM, 1.0f);
    sgemm_nt_kernel<<<gg, 256>>>(x,  weffv, bv, v1, MTOT, EDIM, EDIM, 1.0f);
    sgemm_nt_kernel<<<gg, 256>>>(q1, Wq,    bq, qq, MTOT, EDIM, EDIM, 0.125f); // HD^-0.5
    sgemm_nt_kernel<<<gg, 256>>>(k1, Wk,    bk, kk, MTOT, EDIM, EDIM, 1.0f);
    sgemm_nt_kernel<<<gg, 256>>>(v1, Wv,    bv, vv, MTOT, EDIM, EDIM, 1.0f);

    bucket_kernel<<<(TQ*TQ+255)/256, 256>>>(bucket);
    gate_kernel<<<(BSZ*NH*TQ+255)/256, 256>>>(x, Wg, bg, gru, gate);

    attn_kernel<<<dim3(TQ/BQT, NH, BSZ), 256, attn_smem>>>(qq, kk, vv, gate, bucket, rel, ctx);

    sgemm_nt_kernel<<<gg, 256>>>(ctx, Wo, bo, out, MTOT, EDIM, EDIM, 1.0f);
}

// round 3
// speedup vs baseline: 1.5878x; 1.5878x over previous
#include <cuda_runtime.h>
#include <cuda_bf16.h>
#include <math.h>
#include <stdint.h>

#define BSZ 4
#define TQ 1024
#define EDIM 768
#define NH 12
#define HD 64
#define NB 320
#define MTOT (BSZ*TQ)   // 4096

// ===================== scratch (device globals, no allocation) ==================
__device__ __nv_bfloat16 g_xh[MTOT*EDIM],  g_xl[MTOT*EDIM];
__device__ __nv_bfloat16 g_q1h[MTOT*EDIM], g_q1l[MTOT*EDIM];
__device__ __nv_bfloat16 g_k1h[MTOT*EDIM], g_k1l[MTOT*EDIM];
__device__ __nv_bfloat16 g_v1h[MTOT*EDIM], g_v1l[MTOT*EDIM];
__device__ __nv_bfloat16 g_ctxh[MTOT*EDIM],g_ctxl[MTOT*EDIM];
__device__ __nv_bfloat16 g_weqh[EDIM*EDIM], g_weql[EDIM*EDIM];
__device__ __nv_bfloat16 g_wekh[EDIM*EDIM], g_wekl[EDIM*EDIM];
__device__ __nv_bfloat16 g_wevh[EDIM*EDIM], g_wevl[EDIM*EDIM];
__device__ __nv_bfloat16 g_wqh[EDIM*EDIM],  g_wql[EDIM*EDIM];
__device__ __nv_bfloat16 g_wkh[EDIM*EDIM],  g_wkl[EDIM*EDIM];
__device__ __nv_bfloat16 g_wvh[EDIM*EDIM],  g_wvl[EDIM*EDIM];
__device__ __nv_bfloat16 g_woh[EDIM*EDIM],  g_wol[EDIM*EDIM];
__device__ float g_qq[MTOT*EDIM], g_kk[MTOT*EDIM], g_vv[MTOT*EDIM], g_ctx[MTOT*EDIM];
__device__ float g_gate[BSZ*NH*TQ];
__device__ int   g_bucket[TQ*TQ];

// ===================== PTX helpers (arch-agnostic only!) =========================
__device__ __forceinline__ uint32_t smem_u32(const void* p) {
    uint32_t a;
    asm("{ .reg .u64 t; cvta.to.shared.u64 t, %1; cvt.u32.u64 %0, t; }" : "=r"(a) : "l"(p));
    return a;
}
__device__ __forceinline__ void cp16g(uint32_t dst, const void* src) {
    uint64_t g = (uint64_t)__cvta_generic_to_global(src);
    asm volatile("cp.async.cg.shared.global [%0], [%1], 16;" :: "r"(dst), "l"(g) : "memory");
}
__device__ __forceinline__ void cp_commit() { asm volatile("cp.async.commit_group;" ::: "memory"); }
template<int N> __device__ __forceinline__ void cp_wait() {
    asm volatile("cp.async.wait_group %0;" :: "n"(N) : "memory");
}
__device__ __forceinline__ void ldsm_x4(uint32_t* r, uint32_t addr) {
    asm volatile("ldmatrix.sync.aligned.m8n8.x4.shared.b16 {%0,%1,%2,%3}, [%4];"
        : "=r"(r[0]), "=r"(r[1]), "=r"(r[2]), "=r"(r[3]) : "r"(addr));
}
__device__ __forceinline__ void mma16816(float* c, const uint32_t* a, const uint32_t* b) {
    asm volatile(
        "mma.sync.aligned.m16n8k16.row.col.f32.bf16.bf16.f32 "
        "{%0,%1,%2,%3}, {%4,%5,%6,%7}, {%8,%9}, {%0,%1,%2,%3};"
        : "+f"(c[0]), "+f"(c[1]), "+f"(c[2]), "+f"(c[3])
        : "r"(a[0]), "r"(a[1]), "r"(a[2]), "r"(a[3]), "r"(b[0]), "r"(b[1]));
}

// ===================== HMMA GEMM: C[m,n] = scale*(sum_k A[m,k]*B[n,k] + bias[n]) =
// A = Ah+Al (bf16 hi/lo split of fp32), B = Bh+Bl. 3-term product, fp32 accum.
#define BM 128
#define BN 128
#define BK 32
#define KST 40                          // padded bf16 elems per smem row (80 B)
#define STAGES 4
#define NCHUNKS (EDIM/BK)               // 24
#define ARR_BYTES (128*KST*2)           // 10240
#define STAGE_BYTES (4*ARR_BYTES)       // 40960
#define SM_AH 0
#define SM_AL (ARR_BYTES)
#define SM_BH (2*ARR_BYTES)
#define SM_BL (3*ARR_BYTES)
#define GEMM_SMEM (STAGES*STAGE_BYTES + 512)   // 164352

__device__ __forceinline__ void load_chunk(
    uint32_t st, int chunk, int tid, int m0, int n0,
    const __nv_bfloat16* __restrict__ Ah, const __nv_bfloat16* __restrict__ Al,
    const __nv_bfloat16* __restrict__ Bh, const __nv_bfloat16* __restrict__ Bl)
{
    const int kc = chunk * BK;
#pragma unroll
    for (int i = 0; i < 2; i++) {
        int t = tid + i*256;            // 0..511
        int r = t >> 2;                 // row 0..127
        int seg = t & 3;                // 16B segment 0..3
        uint32_t so = (uint32_t)(r*(KST*2) + seg*16);
        size_t goA = (size_t)(m0 + r)*EDIM + kc + seg*8;
        cp16g(st + SM_AH + so, Ah + goA);
        cp16g(st + SM_AL + so, Al + goA);
        size_t goB = (size_t)(n0 + r)*EDIM + kc + seg*8;
        cp16g(st + SM_BH + so, Bh + goB);
        cp16g(st + SM_BL + so, Bl + goB);
    }
    cp_commit();
}

__global__ __launch_bounds__(256, 1) void hmma_gemm_kernel(
    const __nv_bfloat16* __restrict__ Ah, const __nv_bfloat16* __restrict__ Al,
    const __nv_bfloat16* __restrict__ Bh, const __nv_bfloat16* __restrict__ Bl,
    const float* __restrict__ bias, float scale,
    float* __restrict__ outF, __nv_bfloat16* __restrict__ outH, __nv_bfloat16* __restrict__ outL)
{
    extern __shared__ __align__(256) char smem[];
    const uint32_t sb = smem_u32(smem);
    const int tid  = threadIdx.x;
    const int lane = tid & 31;
    const int wid  = tid >> 5;
    const int warp_m = wid >> 2;        // 0..1  (64 rows each)
    const int warp_n = wid & 3;         // 0..3  (32 cols each)
    const int m0 = blockIdx.y * BM;
    const int n0 = blockIdx.x * BN;
    float* sbias = (float*)(smem + STAGES*STAGE_BYTES);
    if (tid < BN) sbias[tid] = bias[n0 + tid];

    float acc[4][4][4];
#pragma unroll
    for (int mi = 0; mi < 4; mi++)
#pragma unroll
        for (int ni = 0; ni < 4; ni++)
#pragma unroll
            for (int r = 0; r < 4; r++) acc[mi][ni][r] = 0.f;

    // preload STAGES-1 chunks
#pragma unroll
    for (int s = 0; s < STAGES-1; s++)
        load_chunk(sb + s*STAGE_BYTES, s, tid, m0, n0, Ah, Al, Bh, Bl);

    // per-thread ldmatrix offsets
    const int a_row = warp_m*64 + (lane & 15);         // + mi*16
    const int a_col = (lane >> 4) * 8;                 // elems
    const int b_row = warp_n*32 + (lane & 7) + ((lane >> 4) << 3);  // + nn*16
    const int b_col = ((lane >> 3) & 1) * 8;           // elems

    for (int c = 0; c < NCHUNKS; c++) {
        cp_wait<STAGES-2>();
        __syncthreads();
        if (c + STAGES-1 < NCHUNKS)
            load_chunk(sb + ((c + STAGES-1) % STAGES)*STAGE_BYTES, c + STAGES-1,
                       tid, m0, n0, Ah, Al, Bh, Bl);
        else
            cp_commit();   // keep group count advancing so cp_wait<2> frees chunk c

        const uint32_t stg = sb + (c % STAGES)*STAGE_BYTES;
#pragma unroll
        for (int kk = 0; kk < 2; kk++) {
            const uint32_t kof = kk*16;
            uint32_t ah[4][4], al[4][4];
#pragma unroll
            for (int mi = 0; mi < 4; mi++) {
                uint32_t ao = (uint32_t)((a_row + mi*16)*(KST*2) + (kof + a_col)*2);
                ldsm_x4(ah[mi], stg + SM_AH + ao);
                ldsm_x4(al[mi], stg + SM_AL + ao);
            }
            uint32_t bh[4][2], bl[4][2];
#pragma unroll
            for (int nn = 0; nn < 2; nn++) {
                uint32_t bo = (uint32_t)((b_row + nn*16)*(KST*2) + (kof + b_col)*2);
                uint32_t t[4];
                ldsm_x4(t, stg + SM_BH + bo);
                bh[nn*2][0] = t[0]; bh[nn*2][1] = t[1];
                bh[nn*2+1][0] = t[2]; bh[nn*2+1][1] = t[3];
                ldsm_x4(t, stg + SM_BL + bo);
                bl[nn*2][0] = t[0]; bl[nn*2][1] = t[1];
                bl[nn*2+1][0] = t[2]; bl[nn*2+1][1] = t[3];
            }
#pragma unroll
            for (int mi = 0; mi < 4; mi++)
#pragma unroll
                for (int ni = 0; ni < 4; ni++) {
                    mma16816(acc[mi][ni], ah[mi], bh[ni]);
                    mma16816(acc[mi][ni], ah[mi], bl[ni]);
                    mma16816(acc[mi][ni], al[mi], bh[ni]);
                }
        }
    }
    __syncthreads();

    // epilogue: bias + scale, vectorized stores
#pragma unroll
    for (int mi = 0; mi < 4; mi++) {
#pragma unroll
        for (int ni = 0; ni < 4; ni++) {
            int colL = warp_n*32 + ni*8 + (lane & 3)*2;
            int col  = n0 + colL;
            int row0 = m0 + warp_m*64 + mi*16 + (lane >> 2);
            float b0 = sbias[colL], b1 = sbias[colL+1];
            float v00 = scale*(acc[mi][ni][0] + b0);
            float v01 = scale*(acc[mi][ni][1] + b1);
            float v10 = scale*(acc[mi][ni][2] + b0);
            float v11 = scale*(acc[mi][ni][3] + b1);
            if (outF) {
                *(float2*)(outF + (size_t)row0*EDIM + col)     = make_float2(v00, v01);
                *(float2*)(outF + (size_t)(row0+8)*EDIM + col) = make_float2(v10, v11);
            }
            if (outH) {
                __nv_bfloat16 h00 = __float2bfloat16(v00);
                __nv_bfloat16 h01 = __float2bfloat16(v01);
                __nv_bfloat16 h10 = __float2bfloat16(v10);
                __nv_bfloat16 h11 = __float2bfloat16(v11);
                __nv_bfloat162 p;
                p.x = h00; p.y = h01;
                *(__nv_bfloat162*)(outH + (size_t)row0*EDIM + col) = p;
                p.x = h10; p.y = h11;
                *(__nv_bfloat162*)(outH + (size_t)(row0+8)*EDIM + col) = p;
                p.x = __float2bfloat16(v00 - __bfloat162float(h00));
                p.y = __float2bfloat16(v01 - __bfloat162float(h01));
                *(__nv_bfloat162*)(outL + (size_t)row0*EDIM + col) = p;
                p.x = __float2bfloat16(v10 - __bfloat162float(h10));
                p.y = __float2bfloat16(v11 - __bfloat162float(h11));
                *(__nv_bfloat162*)(outL + (size_t)(row0+8)*EDIM + col) = p;
            }
        }
    }
}

// ===================== weight prep =============================================
__global__ void build_weff_hl_kernel(const float* __restrict__ W,
                                     const float* __restrict__ A,   // [2,E]
                                     const float* __restrict__ Bm,  // [E,2]
                                     __nv_bfloat16* __restrict__ oh,
                                     __nv_bfloat16* __restrict__ ol)
{
    int idx = blockIdx.x * blockDim.x + threadIdx.x;
    if (idx >= EDIM*EDIM) return;
    int o = idx / EDIM;
    int e = idx - o*EDIM;
    float w = W[idx] + 0.5f * (Bm[o*2+0]*A[e] + Bm[o*2+1]*A[EDIM + e]);
    __nv_bfloat16 h = __float2bfloat16(w);
    oh[idx] = h;
    ol[idx] = __float2bfloat16(w - __bfloat162float(h));
}

__global__ void f32_to_hl_kernel(const float* __restrict__ in,
                                 __nv_bfloat16* __restrict__ oh,
                                 __nv_bfloat16* __restrict__ ol, int n)
{
    int idx = blockIdx.x * blockDim.x + threadIdx.x;
    if (idx >= n) return;
    float v = in[idx];
    __nv_bfloat16 h = __float2bfloat16(v);
    oh[idx] = h;
    ol[idx] = __float2bfloat16(v - __bfloat162float(h));
}

// ===================== bucket table ============================================
__global__ void bucket_kernel(int* __restrict__ bucket)
{
    int idx = blockIdx.x * blockDim.x + threadIdx.x;
    if (idx >= TQ*TQ) return;
    int i = idx / TQ;
    int j = idx - i*TQ;
    int rel = j - i;
    const int nb = NB/2;
    const int max_exact = nb/2;
    int b = (rel > 0) ? nb : 0;
    int r = abs(rel);
    if (r < max_exact) {
        b += r;
    } else {
        float log_ratio = logf((float)r / (float)max_exact);
        float denom = logf(800.0f / (float)max_exact);
        int large = max_exact + (int)(log_ratio / denom * (float)(nb - max_exact));
        if (large > nb - 1) large = nb - 1;
        b += large;
    }
    bucket[idx] = b;
}

// ===================== gate ====================================================
__global__ void gate_kernel(const float* __restrict__ x,
                            const float* __restrict__ Wg,
                            const float* __restrict__ bg,
                            const float* __restrict__ gru,
                            float* __restrict__ gate)
{
    __shared__ float sWg[8*HD];
    __shared__ float sbg[8];
    int tid = threadIdx.x;
    for (int i = tid; i < 8*HD; i += blockDim.x) sWg[i] = Wg[i];
    if (tid < 8) sbg[tid] = bg[tid];
    __syncthreads();

    int idx = blockIdx.x * blockDim.x + tid;
    if (idx >= BSZ*NH*TQ) return;
    int t = idx % TQ;
    int h = (idx / TQ) % NH;
    int b = idx / (TQ*NH);

    const float* xp = x + ((size_t)b*TQ + t)*EDIM + h*HD;
    float gp[8];
#pragma unroll
    for (int e = 0; e < 8; e++) gp[e] = sbg[e];
#pragma unroll
    for (int d4 = 0; d4 < HD; d4 += 4) {
        float4 xv = *(const float4*)(xp + d4);
#pragma unroll
        for (int e = 0; e < 8; e++) {
            gp[e] = fmaf(xv.x, sWg[e*HD + d4+0], gp[e]);
            gp[e] = fmaf(xv.y, sWg[e*HD + d4+1], gp[e]);
            gp[e] = fmaf(xv.z, sWg[e*HD + d4+2], gp[e]);
            gp[e] = fmaf(xv.w, sWg[e*HD + d4+3], gp[e]);
        }
    }
    float s0 = gp[0]+gp[1]+gp[2]+gp[3];
    float s1 = gp[4]+gp[5]+gp[6]+gp[7];
    float ga = 1.0f / (1.0f + __expf(-s0));
    float gb = 1.0f / (1.0f + __expf(-s1));
    gate[idx] = ga * (gb * gru[h] - 1.0f) + 2.0f;
}

// ===================== flash attention (fp32) ==================================
#define BQT 64
#define BKT 64
#define SP  65

__global__ __launch_bounds__(256) void attn_kernel(
    const float* __restrict__ q, const float* __restrict__ k, const float* __restrict__ v,
    const float* __restrict__ gate, const int* __restrict__ bucket,
    const float* __restrict__ rel_embed,
    float* __restrict__ ctx)
{
    extern __shared__ float fsmem[];
    float* Qs = fsmem;
    float* Ks = Qs + BQT*SP;
    float* Vs = Ks + BKT*SP;
    float* Ps = Vs + BKT*SP;
    float* relc = Ps + BQT*SP;

    const int q0  = blockIdx.x * BQT;
    const int h   = blockIdx.y;
    const int b   = blockIdx.z;
    const int tid = threadIdx.x;
    const int tx  = tid & 15;
    const int ty  = tid >> 4;

    const size_t base = ((size_t)b*TQ)*EDIM + h*HD;

    for (int i = tid; i < NB; i += 256) relc[i] = rel_embed[(size_t)i*NH + h];

#pragma unroll
    for (int p = 0; p < 4; p++) {
        int id = tid + p*256;
        int r = id >> 4;
        int c = (id & 15) * 4;
        float4 v4 = *(const float4*)(q + base + (size_t)(q0 + r)*EDIM + c);
        Qs[r*SP + c+0] = v4.x; Qs[r*SP + c+1] = v4.y; Qs[r*SP + c+2] = v4.z; Qs[r*SP + c+3] = v4.w;
    }

    float m[4], l[4], grow[4];
    float acc[4][4];
#pragma unroll
    for (int i = 0; i < 4; i++) {
        m[i] = -1e30f; l[i] = 0.f;
        grow[i] = gate[((size_t)b*NH + h)*TQ + q0 + ty*4 + i];
#pragma unroll
        for (int j = 0; j < 4; j++) acc[i][j] = 0.f;
    }

    for (int k0 = 0; k0 < TQ; k0 += BKT) {
        __syncthreads();
#pragma unroll
        for (int p = 0; p < 4; p++) {
            int id = tid + p*256;
            int r = id >> 4;
            int c = (id & 15) * 4;
            float4 kv = *(const float4*)(k + base + (size_t)(k0 + r)*EDIM + c);
            Ks[r*SP + c+0] = kv.x; Ks[r*SP + c+1] = kv.y; Ks[r*SP + c+2] = kv.z; Ks[r*SP + c+3] = kv.w;
            float4 vv = *(const float4*)(v + base + (size_t)(k0 + r)*EDIM + c);
            Vs[r*SP + c+0] = vv.x; Vs[r*SP + c+1] = vv.y; Vs[r*SP + c+2] = vv.z; Vs[r*SP + c+3] = vv.w;
        }
        __syncthreads();

        float s[4][4];
#pragma unroll
        for (int i = 0; i < 4; i++)
#pragma unroll
            for (int j = 0; j < 4; j++) s[i][j] = 0.f;
#pragma unroll 8
        for (int d = 0; d < HD; d++) {
            float qa[4], kb[4];
#pragma unroll
            for (int i = 0; i < 4; i++) qa[i] = Qs[(ty*4+i)*SP + d];
#pragma unroll
            for (int j = 0; j < 4; j++) kb[j] = Ks[(tx*4+j)*SP + d];
#pragma unroll
            for (int i = 0; i < 4; i++)
#pragma unroll
                for (int j = 0; j < 4; j++) s[i][j] = fmaf(qa[i], kb[j], s[i][j]);
        }

#pragma unroll
        for (int i = 0; i < 4; i++) {
            const int* brow = bucket + (size_t)(q0 + ty*4 + i)*TQ + k0;
#pragma unroll
            for (int j = 0; j < 4; j++)
                s[i][j] = fmaf(grow[i], relc[brow[tx*4 + j]], s[i][j]);
        }

#pragma unroll
        for (int i = 0; i < 4; i++) {
            float tm = fmaxf(fmaxf(s[i][0], s[i][1]), fmaxf(s[i][2], s[i][3]));
#pragma unroll
            for (int off = 1; off < 16; off <<= 1)
                tm = fmaxf(tm, __shfl_xor_sync(0xffffffffu, tm, off));
            float mn = fmaxf(m[i], tm);
            float corr = __expf(m[i] - mn);
            float psum = 0.f;
#pragma unroll
            for (int j = 0; j < 4; j++) {
                s[i][j] = __expf(s[i][j] - mn);
                psum += s[i][j];
            }
#pragma unroll
            for (int off = 1; off < 16; off <<= 1)
                psum += __shfl_xor_sync(0xffffffffu, psum, off);
            l[i] = l[i]*corr + psum;
            m[i] = mn;
#pragma unroll
            for (int j = 0; j < 4; j++) acc[i][j] *= corr;
        }

#pragma unroll
        for (int i = 0; i < 4; i++)
#pragma unroll
            for (int j = 0; j < 4; j++)
                Ps[(ty*4+i)*SP + tx*4+j] = s[i][j];
        __syncthreads();

#pragma unroll 8
        for (int kc = 0; kc < BKT; kc++) {
            float pv[4], vv[4];
#pragma unroll
            for (int i = 0; i < 4; i++) pv[i] = Ps[(ty*4+i)*SP + kc];
#pragma unroll
            for (int j = 0; j < 4; j++) vv[j] = Vs[kc*SP + tx*4+j];
#pragma unroll
            for (int i = 0; i < 4; i++)
#pragma unroll
                for (int j = 0; j < 4; j++) acc[i][j] = fmaf(pv[i], vv[j], acc[i][j]);
        }
    }

#pragma unroll
    for (int i = 0; i < 4; i++) {
        float inv = 1.0f / l[i];
#pragma unroll
        for (int j = 0; j < 4; j++)
            ctx[base + (size_t)(q0 + ty*4 + i)*EDIM + tx*4 + j] = acc[i][j] * inv;
    }
}

// ===================== launch ===================================================
extern "C" void kernel_launch(void* const* d_in, const int* in_sizes, int n_in,
                              void* d_out, int out_size)
{
    const float* x   = (const float*)d_in[0];
    const float* Wq  = (const float*)d_in[1];
    const float* bq  = (const float*)d_in[2];
    const float* Wk  = (const float*)d_in[3];
    const float* bk  = (const float*)d_in[4];
    const float* Wv  = (const float*)d_in[5];
    const float* bv  = (const float*)d_in[6];
    const float* Aq  = (const float*)d_in[7];
    const float* Bq  = (const float*)d_in[8];
    const float* Ak  = (const float*)d_in[9];
    const float* Bk  = (const float*)d_in[10];
    const float* Av  = (const float*)d_in[11];
    const float* Bv  = (const float*)d_in[12];
    const float* Wo  = (const float*)d_in[13];
    const float* bo  = (const float*)d_in[14];
    const float* Wg  = (const float*)d_in[15];
    const float* bg  = (const float*)d_in[16];
    const float* gru = (const float*)d_in[17];
    const float* rel = (const float*)d_in[18];
    float* out = (float*)d_out;

    __nv_bfloat16 *xh,*xl,*q1h,*q1l,*k1h,*k1l,*v1h,*v1l,*ctxh,*ctxl;
    __nv_bfloat16 *weqh,*weql,*wekh,*wekl,*wevh,*wevl,*wqh,*wql,*wkh,*wkl,*wvh,*wvl,*woh,*wol;
    float *qq,*kk,*vv,*ctx,*gate;
    int* bucket;
    cudaGetSymbolAddress((void**)&xh, g_xh);   cudaGetSymbolAddress((void**)&xl, g_xl);
    cudaGetSymbolAddress((void**)&q1h, g_q1h); cudaGetSymbolAddress((void**)&q1l, g_q1l);
    cudaGetSymbolAddress((void**)&k1h, g_k1h); cudaGetSymbolAddress((void**)&k1l, g_k1l);
    cudaGetSymbolAddress((void**)&v1h, g_v1h); cudaGetSymbolAddress((void**)&v1l, g_v1l);
    cudaGetSymbolAddress((void**)&ctxh, g_ctxh); cudaGetSymbolAddress((void**)&ctxl, g_ctxl);
    cudaGetSymbolAddress((void**)&weqh, g_weqh); cudaGetSymbolAddress((void**)&weql, g_weql);
    cudaGetSymbolAddress((void**)&wekh, g_wekh); cudaGetSymbolAddress((void**)&wekl, g_wekl);
    cudaGetSymbolAddress((void**)&wevh, g_wevh); cudaGetSymbolAddress((void**)&wevl, g_wevl);
    cudaGetSymbolAddress((void**)&wqh, g_wqh);   cudaGetSymbolAddress((void**)&wql, g_wql);
    cudaGetSymbolAddress((void**)&wkh, g_wkh);   cudaGetSymbolAddress((void**)&wkl, g_wkl);
    cudaGetSymbolAddress((void**)&wvh, g_wvh);   cudaGetSymbolAddress((void**)&wvl, g_wvl);
    cudaGetSymbolAddress((void**)&woh, g_woh);   cudaGetSymbolAddress((void**)&wol, g_wol);
    cudaGetSymbolAddress((void**)&qq, g_qq);     cudaGetSymbolAddress((void**)&kk, g_kk);
    cudaGetSymbolAddress((void**)&vv, g_vv);     cudaGetSymbolAddress((void**)&ctx, g_ctx);
    cudaGetSymbolAddress((void**)&gate, g_gate); cudaGetSymbolAddress((void**)&bucket, g_bucket);

    cudaFuncSetAttribute(hmma_gemm_kernel, cudaFuncAttributeMaxDynamicSharedMemorySize, GEMM_SMEM);
    const int attn_smem = (4*BQT*SP + NB) * (int)sizeof(float);
    cudaFuncSetAttribute(attn_kernel, cudaFuncAttributeMaxDynamicSharedMemorySize, attn_smem);

    const int nw = EDIM*EDIM;
    const int nx = MTOT*EDIM;

    // weight prep: folded-LoRA weights + second-projection weights as bf16 hi/lo
    build_weff_hl_kernel<<<(nw+255)/256, 256>>>(Wq, Aq, Bq, weqh, weql);
    build_weff_hl_kernel<<<(nw+255)/256, 256>>>(Wk, Ak, Bk, wekh, wekl);
    build_weff_hl_kernel<<<(nw+255)/256, 256>>>(Wv, Av, Bv, wevh, wevl);
    f32_to_hl_kernel<<<(nw+255)/256, 256>>>(Wq, wqh, wql, nw);
    f32_to_hl_kernel<<<(nw+255)/256, 256>>>(Wk, wkh, wkl, nw);
    f32_to_hl_kernel<<<(nw+255)/256, 256>>>(Wv, wvh, wvl, nw);
    f32_to_hl_kernel<<<(nw+255)/256, 256>>>(Wo, woh, wol, nw);
    f32_to_hl_kernel<<<(nx+255)/256, 256>>>(x, xh, xl, nx);

    dim3 gg(EDIM/BN, MTOT/BM);   // (6, 32) = 192 CTAs
    // first projections (q1,k1,v1) -> bf16 hi/lo only
    hmma_gemm_kernel<<<gg, 256, GEMM_SMEM>>>(xh, xl, weqh, weql, bq, 1.0f, nullptr, q1h, q1l);
    hmma_gemm_kernel<<<gg, 256, GEMM_SMEM>>>(xh, xl, wekh, wekl, bk, 1.0f, nullptr, k1h, k1l);
    hmma_gemm_kernel<<<gg, 256, GEMM_SMEM>>>(xh, xl, wevh, wevl, bv, 1.0f, nullptr, v1h, v1l);
    // second projections -> fp32 for attention
    hmma_gemm_kernel<<<gg, 256, GEMM_SMEM>>>(q1h, q1l, wqh, wql, bq, 0.125f, qq, nullptr, nullptr);
    hmma_gemm_kernel<<<gg, 256, GEMM_SMEM>>>(k1h, k1l, wkh, wkl, bk, 1.0f,   kk, nullptr, nullptr);
    hmma_gemm_kernel<<<gg, 256, GEMM_SMEM>>>(v1h, v1l, wvh, wvl, bv, 1.0f,   vv, nullptr, nullptr);

    bucket_kernel<<<(TQ*TQ+255)/256, 256>>>(bucket);
    gate_kernel<<<(BSZ*NH*TQ+255)/256, 256>>>(x, Wg, bg, gru, gate);

    attn_kernel<<<dim3(TQ/BQT, NH, BSZ), 256, attn_smem>>>(qq, kk, vv, gate, bucket, rel, ctx);

    f32_to_hl_kernel<<<(nx+255)/256, 256>>>(ctx, ctxh, ctxl, nx);
    hmma_gemm_kernel<<<gg, 256, GEMM_SMEM>>>(ctxh, ctxl, woh, wol, bo, 1.0f, out, nullptr, nullptr);
}

// round 4
// speedup vs baseline: 2.4029x; 1.5133x over previous
#include <cuda_runtime.h>
#include <cuda_bf16.h>
#include <math.h>
#include <stdint.h>

#define BSZ 4
#define TQ 1024
#define EDIM 768
#define NH 12
#define HD 64
#define NB 320
#define MTOT (BSZ*TQ)   // 4096

// ===================== scratch (device globals, no allocation) ==================
__device__ __nv_bfloat16 g_xh[MTOT*EDIM],  g_xl[MTOT*EDIM];
__device__ __nv_bfloat16 g_q1h[MTOT*EDIM], g_q1l[MTOT*EDIM];
__device__ __nv_bfloat16 g_k1h[MTOT*EDIM], g_k1l[MTOT*EDIM];
__device__ __nv_bfloat16 g_v1h[MTOT*EDIM], g_v1l[MTOT*EDIM];
__device__ __nv_bfloat16 g_q2h[MTOT*EDIM], g_q2l[MTOT*EDIM];
__device__ __nv_bfloat16 g_k2h[MTOT*EDIM], g_k2l[MTOT*EDIM];
__device__ __nv_bfloat16 g_v2h[MTOT*EDIM], g_v2l[MTOT*EDIM];
__device__ __nv_bfloat16 g_ctxh[MTOT*EDIM],g_ctxl[MTOT*EDIM];
__device__ __nv_bfloat16 g_weqh[EDIM*EDIM], g_weql[EDIM*EDIM];
__device__ __nv_bfloat16 g_wekh[EDIM*EDIM], g_wekl[EDIM*EDIM];
__device__ __nv_bfloat16 g_wevh[EDIM*EDIM], g_wevl[EDIM*EDIM];
__device__ __nv_bfloat16 g_wqh[EDIM*EDIM],  g_wql[EDIM*EDIM];
__device__ __nv_bfloat16 g_wkh[EDIM*EDIM],  g_wkl[EDIM*EDIM];
__device__ __nv_bfloat16 g_wvh[EDIM*EDIM],  g_wvl[EDIM*EDIM];
__device__ __nv_bfloat16 g_woh[EDIM*EDIM],  g_wol[EDIM*EDIM];
__device__ float g_gate[BSZ*NH*TQ];
__device__ float g_relb[NH*2048];

// ===================== PTX helpers (arch-agnostic only!) =========================
__device__ __forceinline__ uint32_t smem_u32(const void* p) {
    uint32_t a;
    asm("{ .reg .u64 t; cvta.to.shared.u64 t, %1; cvt.u32.u64 %0, t; }" : "=r"(a) : "l"(p));
    return a;
}
__device__ __forceinline__ void cp16g(uint32_t dst, const void* src) {
    uint64_t g = (uint64_t)__cvta_generic_to_global(src);
    asm volatile("cp.async.cg.shared.global [%0], [%1], 16;" :: "r"(dst), "l"(g) : "memory");
}
__device__ __forceinline__ void cp_commit() { asm volatile("cp.async.commit_group;" ::: "memory"); }
template<int N> __device__ __forceinline__ void cp_wait() {
    asm volatile("cp.async.wait_group %0;" :: "n"(N) : "memory");
}
__device__ __forceinline__ void ldsm_x4(uint32_t* r, uint32_t addr) {
    asm volatile("ldmatrix.sync.aligned.m8n8.x4.shared.b16 {%0,%1,%2,%3}, [%4];"
        : "=r"(r[0]), "=r"(r[1]), "=r"(r[2]), "=r"(r[3]) : "r"(addr));
}
__device__ __forceinline__ void ldsm_x4_t(uint32_t* r, uint32_t addr) {
    asm volatile("ldmatrix.sync.aligned.m8n8.x4.trans.shared.b16 {%0,%1,%2,%3}, [%4];"
        : "=r"(r[0]), "=r"(r[1]), "=r"(r[2]), "=r"(r[3]) : "r"(addr));
}
__device__ __forceinline__ void mma16816(float* c, const uint32_t* a, const uint32_t* b) {
    asm volatile(
        "mma.sync.aligned.m16n8k16.row.col.f32.bf16.bf16.f32 "
        "{%0,%1,%2,%3}, {%4,%5,%6,%7}, {%8,%9}, {%0,%1,%2,%3};"
        : "+f"(c[0]), "+f"(c[1]), "+f"(c[2]), "+f"(c[3])
        : "r"(a[0]), "r"(a[1]), "r"(a[2]), "r"(a[3]), "r"(b[0]), "r"(b[1]));
}
__device__ __forceinline__ uint32_t packbf2(float a, float b) {
    __nv_bfloat162 t;
    t.x = __float2bfloat16(a); t.y = __float2bfloat16(b);
    return *reinterpret_cast<uint32_t*>(&t);
}
__device__ __forceinline__ uint32_t packbf2_res(float a, float b, uint32_t hp) {
    __nv_bfloat162 t = *reinterpret_cast<__nv_bfloat162*>(&hp);
    return packbf2(a - __bfloat162float(t.x), b - __bfloat162float(t.y));
}

// ===================== HMMA GEMM (unchanged engine from R3) =====================
#define BM 128
#define BN 128
#define BK 32
#define KST 40
#define STAGES 4
#define NCHUNKS (EDIM/BK)               // 24
#define ARR_BYTES (128*KST*2)           // 10240
#define STAGE_BYTES (4*ARR_BYTES)       // 40960
#define SM_AH 0
#define SM_AL (ARR_BYTES)
#define SM_BH (2*ARR_BYTES)
#define SM_BL (3*ARR_BYTES)
#define GEMM_SMEM (STAGES*STAGE_BYTES + 512)

__device__ __forceinline__ void load_chunk(
    uint32_t st, int chunk, int tid, int m0, int n0,
    const __nv_bfloat16* __restrict__ Ah, const __nv_bfloat16* __restrict__ Al,
    const __nv_bfloat16* __restrict__ Bh, const __nv_bfloat16* __restrict__ Bl)
{
    const int kc = chunk * BK;
#pragma unroll
    for (int i = 0; i < 2; i++) {
        int t = tid + i*256;
        int r = t >> 2;
        int seg = t & 3;
        uint32_t so = (uint32_t)(r*(KST*2) + seg*16);
        size_t goA = (size_t)(m0 + r)*EDIM + kc + seg*8;
        cp16g(st + SM_AH + so, Ah + goA);
        cp16g(st + SM_AL + so, Al + goA);
        size_t goB = (size_t)(n0 + r)*EDIM + kc + seg*8;
        cp16g(st + SM_BH + so, Bh + goB);
        cp16g(st + SM_BL + so, Bl + goB);
    }
    cp_commit();
}

__global__ __launch_bounds__(256, 1) void hmma_gemm_kernel(
    const __nv_bfloat16* __restrict__ Ah, const __nv_bfloat16* __restrict__ Al,
    const __nv_bfloat16* __restrict__ Bh, const __nv_bfloat16* __restrict__ Bl,
    const float* __restrict__ bias, float scale,
    float* __restrict__ outF, __nv_bfloat16* __restrict__ outH, __nv_bfloat16* __restrict__ outL)
{
    extern __shared__ __align__(256) char smem[];
    const uint32_t sb = smem_u32(smem);
    const int tid  = threadIdx.x;
    const int lane = tid & 31;
    const int wid  = tid >> 5;
    const int warp_m = wid >> 2;
    const int warp_n = wid & 3;
    const int m0 = blockIdx.y * BM;
    const int n0 = blockIdx.x * BN;
    float* sbias = (float*)(smem + STAGES*STAGE_BYTES);
    if (tid < BN) sbias[tid] = bias[n0 + tid];

    float acc[4][4][4];
#pragma unroll
    for (int mi = 0; mi < 4; mi++)
#pragma unroll
        for (int ni = 0; ni < 4; ni++)
#pragma unroll
            for (int r = 0; r < 4; r++) acc[mi][ni][r] = 0.f;

#pragma unroll
    for (int s = 0; s < STAGES-1; s++)
        load_chunk(sb + s*STAGE_BYTES, s, tid, m0, n0, Ah, Al, Bh, Bl);

    const int a_row = warp_m*64 + (lane & 15);
    const int a_col = (lane >> 4) * 8;
    const int b_row = warp_n*32 + (lane & 7) + ((lane >> 4) << 3);
    const int b_col = ((lane >> 3) & 1) * 8;

    for (int c = 0; c < NCHUNKS; c++) {
        cp_wait<STAGES-2>();
        __syncthreads();
        if (c + STAGES-1 < NCHUNKS)
            load_chunk(sb + ((c + STAGES-1) % STAGES)*STAGE_BYTES, c + STAGES-1,
                       tid, m0, n0, Ah, Al, Bh, Bl);
        else
            cp_commit();

        const uint32_t stg = sb + (c % STAGES)*STAGE_BYTES;
#pragma unroll
        for (int kk = 0; kk < 2; kk++) {
            const uint32_t kof = kk*16;
            uint32_t ah[4][4], al[4][4];
#pragma unroll
            for (int mi = 0; mi < 4; mi++) {
                uint32_t ao = (uint32_t)((a_row + mi*16)*(KST*2) + (kof + a_col)*2);
                ldsm_x4(ah[mi], stg + SM_AH + ao);
                ldsm_x4(al[mi], stg + SM_AL + ao);
            }
            uint32_t bh[4][2], bl[4][2];
#pragma unroll
            for (int nn = 0; nn < 2; nn++) {
                uint32_t bo = (uint32_t)((b_row + nn*16)*(KST*2) + (kof + b_col)*2);
                uint32_t t[4];
                ldsm_x4(t, stg + SM_BH + bo);
                bh[nn*2][0] = t[0]; bh[nn*2][1] = t[1];
                bh[nn*2+1][0] = t[2]; bh[nn*2+1][1] = t[3];
                ldsm_x4(t, stg + SM_BL + bo);
                bl[nn*2][0] = t[0]; bl[nn*2][1] = t[1];
                bl[nn*2+1][0] = t[2]; bl[nn*2+1][1] = t[3];
            }
#pragma unroll
            for (int mi = 0; mi < 4; mi++)
#pragma unroll
                for (int ni = 0; ni < 4; ni++) {
                    mma16816(acc[mi][ni], ah[mi], bh[ni]);
                    mma16816(acc[mi][ni], ah[mi], bl[ni]);
                    mma16816(acc[mi][ni], al[mi], bh[ni]);
                }
        }
    }
    __syncthreads();

#pragma unroll
    for (int mi = 0; mi < 4; mi++) {
#pragma unroll
        for (int ni = 0; ni < 4; ni++) {
            int colL = warp_n*32 + ni*8 + (lane & 3)*2;
            int col  = n0 + colL;
            int row0 = m0 + warp_m*64 + mi*16 + (lane >> 2);
            float b0 = sbias[colL], b1 = sbias[colL+1];
            float v00 = scale*(acc[mi][ni][0] + b0);
            float v01 = scale*(acc[mi][ni][1] + b1);
            float v10 = scale*(acc[mi][ni][2] + b0);
            float v11 = scale*(acc[mi][ni][3] + b1);
            if (outF) {
                *(float2*)(outF + (size_t)row0*EDIM + col)     = make_float2(v00, v01);
                *(float2*)(outF + (size_t)(row0+8)*EDIM + col) = make_float2(v10, v11);
            }
            if (outH) {
                uint32_t h0 = packbf2(v00, v01);
                uint32_t h1 = packbf2(v10, v11);
                *(uint32_t*)(outH + (size_t)row0*EDIM + col)     = h0;
                *(uint32_t*)(outH + (size_t)(row0+8)*EDIM + col) = h1;
                *(uint32_t*)(outL + (size_t)row0*EDIM + col)     = packbf2_res(v00, v01, h0);
                *(uint32_t*)(outL + (size_t)(row0+8)*EDIM + col) = packbf2_res(v10, v11, h1);
            }
        }
    }
}

// ===================== weight / input prep =====================================
__global__ void build_weff_hl_kernel(const float* __restrict__ W,
                                     const float* __restrict__ A,
                                     const float* __restrict__ Bm,
                                     __nv_bfloat16* __restrict__ oh,
                                     __nv_bfloat16* __restrict__ ol)
{
    int idx = blockIdx.x * blockDim.x + threadIdx.x;
    if (idx >= EDIM*EDIM) return;
    int o = idx / EDIM;
    int e = idx - o*EDIM;
    float w = W[idx] + 0.5f * (Bm[o*2+0]*A[e] + Bm[o*2+1]*A[EDIM + e]);
    __nv_bfloat16 h = __float2bfloat16(w);
    oh[idx] = h;
    ol[idx] = __float2bfloat16(w - __bfloat162float(h));
}

__global__ void f32_to_hl_kernel(const float* __restrict__ in,
                                 __nv_bfloat16* __restrict__ oh,
                                 __nv_bfloat16* __restrict__ ol, int n)
{
    int idx = blockIdx.x * blockDim.x + threadIdx.x;
    if (idx >= n) return;
    float v = in[idx];
    __nv_bfloat16 h = __float2bfloat16(v);
    oh[idx] = h;
    ol[idx] = __float2bfloat16(v - __bfloat162float(h));
}

// ===================== rel-pos bias table [NH][2048] ===========================
__global__ void relbias_kernel(const float* __restrict__ rel_embed, float* __restrict__ relb)
{
    int idx = blockIdx.x * blockDim.x + threadIdx.x;
    if (idx >= NH*2047) return;
    int h = idx / 2047;
    int d = idx - h*2047;
    int rel = d - 1023;
    const int nb = NB/2;
    const int max_exact = nb/2;
    int b = (rel > 0) ? nb : 0;
    int r = abs(rel);
    if (r < max_exact) {
        b += r;
    } else {
        float log_ratio = logf((float)r / (float)max_exact);
        float denom = logf(800.0f / (float)max_exact);
        int large = max_exact + (int)(log_ratio / denom * (float)(nb - max_exact));
        if (large > nb - 1) large = nb - 1;
        b += large;
    }
    relb[h*2048 + d] = rel_embed[(size_t)b*NH + h];
}

// ===================== gate ====================================================
__global__ void gate_kernel(const float* __restrict__ x,
                            const float* __restrict__ Wg,
                            const float* __restrict__ bg,
                            const float* __restrict__ gru,
                            float* __restrict__ gate)
{
    __shared__ float sWg[8*HD];
    __shared__ float sbg[8];
    int tid = threadIdx.x;
    for (int i = tid; i < 8*HD; i += blockDim.x) sWg[i] = Wg[i];
    if (tid < 8) sbg[tid] = bg[tid];
    __syncthreads();

    int idx = blockIdx.x * blockDim.x + tid;
    if (idx >= BSZ*NH*TQ) return;
    int t = idx % TQ;
    int h = (idx / TQ) % NH;
    int b = idx / (TQ*NH);

    const float* xp = x + ((size_t)b*TQ + t)*EDIM + h*HD;
    float gp[8];
#pragma unroll
    for (int e = 0; e < 8; e++) gp[e] = sbg[e];
#pragma unroll
    for (int d4 = 0; d4 < HD; d4 += 4) {
        float4 xv = *(const float4*)(xp + d4);
#pragma unroll
        for (int e = 0; e < 8; e++) {
            gp[e] = fmaf(xv.x, sWg[e*HD + d4+0], gp[e]);
            gp[e] = fmaf(xv.y, sWg[e*HD + d4+1], gp[e]);
            gp[e] = fmaf(xv.z, sWg[e*HD + d4+2], gp[e]);
            gp[e] = fmaf(xv.w, sWg[e*HD + d4+3], gp[e]);
        }
    }
    float s0 = gp[0]+gp[1]+gp[2]+gp[3];
    float s1 = gp[4]+gp[5]+gp[6]+gp[7];
    float ga = 1.0f / (1.0f + __expf(-s0));
    float gb = 1.0f / (1.0f + __expf(-s1));
    gate[idx] = ga * (gb * gru[h] - 1.0f) + 2.0f;
}

// ===================== HMMA flash attention =====================================
// BQ=128 q rows per block, 8 warps (16 rows each), BKV=64 kv per tile, HD=64.
// S = (Qh+Ql)(Kh+Kl)^T (3 terms), P split hi/lo, O = (Ph+Pl)(Vh+Vl) (3 terms).
#define AQ 128
#define AKV 64
#define QSTR 72                              // padded bf16 stride
#define A_RELB 0                             // 2048 floats = 8192 B
#define A_QH 8192
#define A_QL (A_QH + AQ*QSTR*2)              // +18432
#define A_KV (A_QL + AQ*QSTR*2)              // 45056
#define KV_ARR (AKV*QSTR*2)                  // 9216
#define KV_STAGE (4*KV_ARR)                  // 36864
#define ATTN_SMEM (A_KV + 2*KV_STAGE)        // 118784
#define NTILES (TQ/AKV)                      // 16

__device__ __forceinline__ void attn_load_kv(
    uint32_t dst, size_t hb, int k0, int tid,
    const __nv_bfloat16* __restrict__ kh, const __nv_bfloat16* __restrict__ kl,
    const __nv_bfloat16* __restrict__ vh, const __nv_bfloat16* __restrict__ vl)
{
#pragma unroll
    for (int i = 0; i < 2; i++) {
        int t = tid + i*256;
        int r = t >> 3;
        int s = t & 7;
        uint32_t so = (uint32_t)(r*QSTR + s*8)*2;
        size_t go = hb + (size_t)(k0 + r)*EDIM + s*8;
        cp16g(dst + 0*KV_ARR + so, kh + go);
        cp16g(dst + 1*KV_ARR + so, kl + go);
        cp16g(dst + 2*KV_ARR + so, vh + go);
        cp16g(dst + 3*KV_ARR + so, vl + go);
    }
    cp_commit();
}

__global__ __launch_bounds__(256, 1) void attn_hmma_kernel(
    const __nv_bfloat16* __restrict__ qh, const __nv_bfloat16* __restrict__ ql,
    const __nv_bfloat16* __restrict__ kh, const __nv_bfloat16* __restrict__ kl,
    const __nv_bfloat16* __restrict__ vh, const __nv_bfloat16* __restrict__ vl,
    const float* __restrict__ gate, const float* __restrict__ relbg,
    __nv_bfloat16* __restrict__ ctxh, __nv_bfloat16* __restrict__ ctxl)
{
    extern __shared__ __align__(256) char asmem[];
    const uint32_t sb = smem_u32(asmem);
    float* relbs = (float*)asmem;
    const int tid  = threadIdx.x;
    const int lane = tid & 31;
    const int w    = tid >> 5;
    const int q0 = blockIdx.x * AQ;
    const int h  = blockIdx.y;
    const int b  = blockIdx.z;
    const size_t hb = (size_t)b*TQ*EDIM + h*HD;

    for (int i = tid; i < 2047; i += 256) relbs[i] = relbg[h*2048 + i];

    // Q tile -> smem (cp.async)
#pragma unroll
    for (int i = 0; i < 4; i++) {
        int t = tid + i*256;
        int r = t >> 3;
        int s = t & 7;
        uint32_t so = (uint32_t)(r*QSTR + s*8)*2;
        size_t go = hb + (size_t)(q0 + r)*EDIM + s*8;
        cp16g(sb + A_QH + so, qh + go);
        cp16g(sb + A_QL + so, ql + go);
    }
    cp_commit();
    attn_load_kv(sb + A_KV, hb, 0, tid, kh, kl, vh, vl);

    const int lq  = lane >> 2;
    const int lc2 = (lane & 3) * 2;
    const int qg0 = q0 + w*16 + lq;           // global q row (upper), +8 lower
    const float grow0 = gate[((size_t)b*NH + h)*TQ + qg0];
    const float grow1 = gate[((size_t)b*NH + h)*TQ + qg0 + 8];

    float m0 = -1e30f, m1 = -1e30f, l0 = 0.f, l1 = 0.f;
    float o[8][4];
#pragma unroll
    for (int nf = 0; nf < 8; nf++)
#pragma unroll
        for (int e = 0; e < 4; e++) o[nf][e] = 0.f;

    uint32_t qhf[4][4], qlf[4][4];

    for (int t = 0; t < NTILES; t++) {
        if (t + 1 < NTILES)
            attn_load_kv(sb + A_KV + ((t+1)&1)*KV_STAGE, hb, (t+1)*AKV, tid, kh, kl, vh, vl);
        if (t + 1 < NTILES) cp_wait<1>(); else cp_wait<0>();
        __syncthreads();

        if (t == 0) {
#pragma unroll
            for (int kk = 0; kk < 4; kk++) {
                uint32_t ao = (uint32_t)(((w*16 + (lane & 15))*QSTR + (lane >> 4)*8 + kk*16)*2);
                ldsm_x4(qhf[kk], sb + A_QH + ao);
                ldsm_x4(qlf[kk], sb + A_QL + ao);
            }
        }
        const uint32_t kv = sb + A_KV + (t & 1)*KV_STAGE;

        // ---- S = Q @ K^T (3-term split) ----
        float s[8][4];
#pragma unroll
        for (int nf = 0; nf < 8; nf++)
#pragma unroll
            for (int e = 0; e < 4; e++) s[nf][e] = 0.f;
#pragma unroll
        for (int kk = 0; kk < 4; kk++) {
#pragma unroll
            for (int nn = 0; nn < 4; nn++) {
                uint32_t bo = (uint32_t)(((nn*16 + (lane & 7) + ((lane >> 4) << 3))*QSTR
                                          + ((lane >> 3) & 1)*8 + kk*16)*2);
                uint32_t th[4], tl[4];
                ldsm_x4(th, kv + 0*KV_ARR + bo);
                ldsm_x4(tl, kv + 1*KV_ARR + bo);
                mma16816(s[2*nn],   qhf[kk], th);
                mma16816(s[2*nn],   qhf[kk], tl);
                mma16816(s[2*nn],   qlf[kk], th);
                mma16816(s[2*nn+1], qhf[kk], th+2);
                mma16816(s[2*nn+1], qhf[kk], tl+2);
                mma16816(s[2*nn+1], qlf[kk], th+2);
            }
        }

        // ---- gated rel-pos bias + online softmax ----
        const int k0 = t*AKV;
        float tm0 = -1e30f, tm1 = -1e30f;
#pragma unroll
        for (int nf = 0; nf < 8; nf++) {
            int d0 = (k0 + nf*8 + lc2) - qg0 + 1023;
            s[nf][0] = fmaf(grow0, relbs[d0],   s[nf][0]);
            s[nf][1] = fmaf(grow0, relbs[d0+1], s[nf][1]);
            s[nf][2] = fmaf(grow1, relbs[d0-8], s[nf][2]);
            s[nf][3] = fmaf(grow1, relbs[d0-7], s[nf][3]);
            tm0 = fmaxf(tm0, fmaxf(s[nf][0], s[nf][1]));
            tm1 = fmaxf(tm1, fmaxf(s[nf][2], s[nf][3]));
        }
#pragma unroll
        for (int off = 1; off < 4; off <<= 1) {
            tm0 = fmaxf(tm0, __shfl_xor_sync(0xffffffffu, tm0, off));
            tm1 = fmaxf(tm1, __shfl_xor_sync(0xffffffffu, tm1, off));
        }
        float mn0 = fmaxf(m0, tm0), mn1 = fmaxf(m1, tm1);
        float corr0 = __expf(m0 - mn0), corr1 = __expf(m1 - mn1);
        float ps0 = 0.f, ps1 = 0.f;
#pragma unroll
        for (int nf = 0; nf < 8; nf++) {
            s[nf][0] = __expf(s[nf][0] - mn0);
            s[nf][1] = __expf(s[nf][1] - mn0);
            s[nf][2] = __expf(s[nf][2] - mn1);
            s[nf][3] = __expf(s[nf][3] - mn1);
            ps0 += s[nf][0] + s[nf][1];
            ps1 += s[nf][2] + s[nf][3];
        }
#pragma unroll
        for (int off = 1; off < 4; off <<= 1) {
            ps0 += __shfl_xor_sync(0xffffffffu, ps0, off);
            ps1 += __shfl_xor_sync(0xffffffffu, ps1, off);
        }
        l0 = l0*corr0 + ps0;  m0 = mn0;
        l1 = l1*corr1 + ps1;  m1 = mn1;
#pragma unroll
        for (int nf = 0; nf < 8; nf++) {
            o[nf][0] *= corr0; o[nf][1] *= corr0;
            o[nf][2] *= corr1; o[nf][3] *= corr1;
        }

        // ---- O += P @ V (P register-resident, 3-term split) ----
#pragma unroll
        for (int kk = 0; kk < 4; kk++) {
            uint32_t aph[4], apl[4];
            aph[0] = packbf2(s[2*kk][0],   s[2*kk][1]);
            aph[1] = packbf2(s[2*kk][2],   s[2*kk][3]);
            aph[2] = packbf2(s[2*kk+1][0], s[2*kk+1][1]);
            aph[3] = packbf2(s[2*kk+1][2], s[2*kk+1][3]);
            apl[0] = packbf2_res(s[2*kk][0],   s[2*kk][1],   aph[0]);
            apl[1] = packbf2_res(s[2*kk][2],   s[2*kk][3],   aph[1]);
            apl[2] = packbf2_res(s[2*kk+1][0], s[2*kk+1][1], aph[2]);
            apl[3] = packbf2_res(s[2*kk+1][2], s[2*kk+1][3], aph[3]);
#pragma unroll
            for (int nn = 0; nn < 4; nn++) {
                uint32_t vo = (uint32_t)(((kk*16 + (lane & 7) + (((lane >> 3) & 1) << 3))*QSTR
                                          + nn*16 + (lane >> 4)*8)*2);
                uint32_t th[4], tl[4];
                ldsm_x4_t(th, kv + 2*KV_ARR + vo);
                ldsm_x4_t(tl, kv + 3*KV_ARR + vo);
                mma16816(o[2*nn],   aph, th);
                mma16816(o[2*nn],   aph, tl);
                mma16816(o[2*nn],   apl, th);
                mma16816(o[2*nn+1], aph, th+2);
                mma16816(o[2*nn+1], aph, tl+2);
                mma16816(o[2*nn+1], apl, th+2);
            }
        }
        __syncthreads();
    }

    // ---- epilogue: normalize, split hi/lo, store ----
    const float inv0 = 1.0f / l0;
    const float inv1 = 1.0f / l1;
#pragma unroll
    for (int nf = 0; nf < 8; nf++) {
        float v00 = o[nf][0]*inv0, v01 = o[nf][1]*inv0;
        float v10 = o[nf][2]*inv1, v11 = o[nf][3]*inv1;
        size_t r0 = hb + (size_t)qg0*EDIM + nf*8 + lc2;
        size_t r1 = r0 + (size_t)8*EDIM;
        uint32_t h0 = packbf2(v00, v01);
        uint32_t h1 = packbf2(v10, v11);
        *(uint32_t*)(ctxh + r0) = h0;
        *(uint32_t*)(ctxh + r1) = h1;
        *(uint32_t*)(ctxl + r0) = packbf2_res(v00, v01, h0);
        *(uint32_t*)(ctxl + r1) = packbf2_res(v10, v11, h1);
    }
}

// ===================== launch ===================================================
extern "C" void kernel_launch(void* const* d_in, const int* in_sizes, int n_in,
                              void* d_out, int out_size)
{
    const float* x   = (const float*)d_in[0];
    const float* Wq  = (const float*)d_in[1];
    const float* bq  = (const float*)d_in[2];
    const float* Wk  = (const float*)d_in[3];
    const float* bk  = (const float*)d_in[4];
    const float* Wv  = (const float*)d_in[5];
    const float* bv  = (const float*)d_in[6];
    const float* Aq  = (const float*)d_in[7];
    const float* Bq  = (const float*)d_in[8];
    const float* Ak  = (const float*)d_in[9];
    const float* Bk  = (const float*)d_in[10];
    const float* Av  = (const float*)d_in[11];
    const float* Bv  = (const float*)d_in[12];
    const float* Wo  = (const float*)d_in[13];
    const float* bo  = (const float*)d_in[14];
    const float* Wg  = (const float*)d_in[15];
    const float* bg  = (const float*)d_in[16];
    const float* gru = (const float*)d_in[17];
    const float* rel = (const float*)d_in[18];
    float* out = (float*)d_out;

    __nv_bfloat16 *xh,*xl,*q1h,*q1l,*k1h,*k1l,*v1h,*v1l;
    __nv_bfloat16 *q2h,*q2l,*k2h,*k2l,*v2h,*v2l,*ctxh,*ctxl;
    __nv_bfloat16 *weqh,*weql,*wekh,*wekl,*wevh,*wevl,*wqh,*wql,*wkh,*wkl,*wvh,*wvl,*woh,*wol;
    float *gate, *relb;
    cudaGetSymbolAddress((void**)&xh, g_xh);   cudaGetSymbolAddress((void**)&xl, g_xl);
    cudaGetSymbolAddress((void**)&q1h, g_q1h); cudaGetSymbolAddress((void**)&q1l, g_q1l);
    cudaGetSymbolAddress((void**)&k1h, g_k1h); cudaGetSymbolAddress((void**)&k1l, g_k1l);
    cudaGetSymbolAddress((void**)&v1h, g_v1h); cudaGetSymbolAddress((void**)&v1l, g_v1l);
    cudaGetSymbolAddress((void**)&q2h, g_q2h); cudaGetSymbolAddress((void**)&q2l, g_q2l);
    cudaGetSymbolAddress((void**)&k2h, g_k2h); cudaGetSymbolAddress((void**)&k2l, g_k2l);
    cudaGetSymbolAddress((void**)&v2h, g_v2h); cudaGetSymbolAddress((void**)&v2l, g_v2l);
    cudaGetSymbolAddress((void**)&ctxh, g_ctxh); cudaGetSymbolAddress((void**)&ctxl, g_ctxl);
    cudaGetSymbolAddress((void**)&weqh, g_weqh); cudaGetSymbolAddress((void**)&weql, g_weql);
    cudaGetSymbolAddress((void**)&wekh, g_wekh); cudaGetSymbolAddress((void**)&wekl, g_wekl);
    cudaGetSymbolAddress((void**)&wevh, g_wevh); cudaGetSymbolAddress((void**)&wevl, g_wevl);
    cudaGetSymbolAddress((void**)&wqh, g_wqh);   cudaGetSymbolAddress((void**)&wql, g_wql);
    cudaGetSymbolAddress((void**)&wkh, g_wkh);   cudaGetSymbolAddress((void**)&wkl, g_wkl);
    cudaGetSymbolAddress((void**)&wvh, g_wvh);   cudaGetSymbolAddress((void**)&wvl, g_wvl);
    cudaGetSymbolAddress((void**)&woh, g_woh);   cudaGetSymbolAddress((void**)&wol, g_wol);
    cudaGetSymbolAddress((void**)&gate, g_gate); cudaGetSymbolAddress((void**)&relb, g_relb);

    cudaFuncSetAttribute(hmma_gemm_kernel, cudaFuncAttributeMaxDynamicSharedMemorySize, GEMM_SMEM);
    cudaFuncSetAttribute(attn_hmma_kernel, cudaFuncAttributeMaxDynamicSharedMemorySize, ATTN_SMEM);

    const int nw = EDIM*EDIM;
    const int nx = MTOT*EDIM;

    build_weff_hl_kernel<<<(nw+255)/256, 256>>>(Wq, Aq, Bq, weqh, weql);
    build_weff_hl_kernel<<<(nw+255)/256, 256>>>(Wk, Ak, Bk, wekh, wekl);
    build_weff_hl_kernel<<<(nw+255)/256, 256>>>(Wv, Av, Bv, wevh, wevl);
    f32_to_hl_kernel<<<(nw+255)/256, 256>>>(Wq, wqh, wql, nw);
    f32_to_hl_kernel<<<(nw+255)/256, 256>>>(Wk, wkh, wkl, nw);
    f32_to_hl_kernel<<<(nw+255)/256, 256>>>(Wv, wvh, wvl, nw);
    f32_to_hl_kernel<<<(nw+255)/256, 256>>>(Wo, woh, wol, nw);
    f32_to_hl_kernel<<<(nx+255)/256, 256>>>(x, xh, xl, nx);
    relbias_kernel<<<(NH*2047+255)/256, 256>>>(rel, relb);
    gate_kernel<<<(BSZ*NH*TQ+255)/256, 256>>>(x, Wg, bg, gru, gate);

    dim3 gg(EDIM/BN, MTOT/BM);
    hmma_gemm_kernel<<<gg, 256, GEMM_SMEM>>>(xh, xl, weqh, weql, bq, 1.0f, nullptr, q1h, q1l);
    hmma_gemm_kernel<<<gg, 256, GEMM_SMEM>>>(xh, xl, wekh, wekl, bk, 1.0f, nullptr, k1h, k1l);
    hmma_gemm_kernel<<<gg, 256, GEMM_SMEM>>>(xh, xl, wevh, wevl, bv, 1.0f, nullptr, v1h, v1l);
    hmma_gemm_kernel<<<gg, 256, GEMM_SMEM>>>(q1h, q1l, wqh, wql, bq, 0.125f, nullptr, q2h, q2l);
    hmma_gemm_kernel<<<gg, 256, GEMM_SMEM>>>(k1h, k1l, wkh, wkl, bk, 1.0f,   nullptr, k2h, k2l);
    hmma_gemm_kernel<<<gg, 256, GEMM_SMEM>>>(v1h, v1l, wvh, wvl, bv, 1.0f,   nullptr, v2h, v2l);

    attn_hmma_kernel<<<dim3(TQ/AQ, NH, BSZ), 256, ATTN_SMEM>>>(
        q2h, q2l, k2h, k2l, v2h, v2l, gate, relb, ctxh, ctxl);

    hmma_gemm_kernel<<<gg, 256, GEMM_SMEM>>>(ctxh, ctxl, woh, wol, bo, 1.0f, out, nullptr, nullptr);
}

// round 5
// speedup vs baseline: 3.8147x; 1.5876x over previous
#include <cuda_runtime.h>
#include <cuda_bf16.h>
#include <math.h>
#include <stdint.h>

#define BSZ 4
#define TQ 1024
#define EDIM 768
#define NH 12
#define HD 64
#define NB 320
#define MTOT (BSZ*TQ)   // 4096

// ===================== scratch (device globals, no allocation) ==================
__device__ __nv_bfloat16 g_xh[MTOT*EDIM],  g_xl[MTOT*EDIM];
__device__ __nv_bfloat16 g_q2h[MTOT*EDIM], g_q2l[MTOT*EDIM];
__device__ __nv_bfloat16 g_k2h[MTOT*EDIM], g_k2l[MTOT*EDIM];
__device__ __nv_bfloat16 g_v2h[MTOT*EDIM], g_v2l[MTOT*EDIM];
__device__ __nv_bfloat16 g_ctxh[MTOT*EDIM],g_ctxl[MTOT*EDIM];
// transposed folded-LoRA weights  WeffT[e,m] = Weff[m,e]
__device__ __nv_bfloat16 g_wetqh[EDIM*EDIM], g_wetql[EDIM*EDIM];
__device__ __nv_bfloat16 g_wetkh[EDIM*EDIM], g_wetkl[EDIM*EDIM];
__device__ __nv_bfloat16 g_wetvh[EDIM*EDIM], g_wetvl[EDIM*EDIM];
// plain weights hi/lo
__device__ __nv_bfloat16 g_wqh[EDIM*EDIM],  g_wql[EDIM*EDIM];
__device__ __nv_bfloat16 g_wkh[EDIM*EDIM],  g_wkl[EDIM*EDIM];
__device__ __nv_bfloat16 g_wvh[EDIM*EDIM],  g_wvl[EDIM*EDIM];
__device__ __nv_bfloat16 g_woh[EDIM*EDIM],  g_wol[EDIM*EDIM];
// combined weights  Wcomb = W @ Weff  [o,e]
__device__ __nv_bfloat16 g_wcqh[EDIM*EDIM], g_wcql[EDIM*EDIM];
__device__ __nv_bfloat16 g_wckh[EDIM*EDIM], g_wckl[EDIM*EDIM];
__device__ __nv_bfloat16 g_wcvh[EDIM*EDIM], g_wcvl[EDIM*EDIM];
__device__ float g_bcomb[3*EDIM];
__device__ float g_gate[BSZ*NH*TQ];
__device__ float g_relb[NH*2048];

// ===================== PTX helpers (arch-agnostic only!) =========================
__device__ __forceinline__ uint32_t smem_u32(const void* p) {
    uint32_t a;
    asm("{ .reg .u64 t; cvta.to.shared.u64 t, %1; cvt.u32.u64 %0, t; }" : "=r"(a) : "l"(p));
    return a;
}
__device__ __forceinline__ void cp16g(uint32_t dst, const void* src) {
    uint64_t g = (uint64_t)__cvta_generic_to_global(src);
    asm volatile("cp.async.cg.shared.global [%0], [%1], 16;" :: "r"(dst), "l"(g) : "memory");
}
__device__ __forceinline__ void cp_commit() { asm volatile("cp.async.commit_group;" ::: "memory"); }
template<int N> __device__ __forceinline__ void cp_wait() {
    asm volatile("cp.async.wait_group %0;" :: "n"(N) : "memory");
}
__device__ __forceinline__ void ldsm_x4(uint32_t* r, uint32_t addr) {
    asm volatile("ldmatrix.sync.aligned.m8n8.x4.shared.b16 {%0,%1,%2,%3}, [%4];"
        : "=r"(r[0]), "=r"(r[1]), "=r"(r[2]), "=r"(r[3]) : "r"(addr));
}
__device__ __forceinline__ void ldsm_x4_t(uint32_t* r, uint32_t addr) {
    asm volatile("ldmatrix.sync.aligned.m8n8.x4.trans.shared.b16 {%0,%1,%2,%3}, [%4];"
        : "=r"(r[0]), "=r"(r[1]), "=r"(r[2]), "=r"(r[3]) : "r"(addr));
}
__device__ __forceinline__ void mma16816(float* c, const uint32_t* a, const uint32_t* b) {
    asm volatile(
        "mma.sync.aligned.m16n8k16.row.col.f32.bf16.bf16.f32 "
        "{%0,%1,%2,%3}, {%4,%5,%6,%7}, {%8,%9}, {%0,%1,%2,%3};"
        : "+f"(c[0]), "+f"(c[1]), "+f"(c[2]), "+f"(c[3])
        : "r"(a[0]), "r"(a[1]), "r"(a[2]), "r"(a[3]), "r"(b[0]), "r"(b[1]));
}
__device__ __forceinline__ uint32_t packbf2(float a, float b) {
    __nv_bfloat162 t;
    t.x = __float2bfloat16(a); t.y = __float2bfloat16(b);
    return *reinterpret_cast<uint32_t*>(&t);
}
__device__ __forceinline__ uint32_t packbf2_res(float a, float b, uint32_t hp) {
    __nv_bfloat162 t = *reinterpret_cast<__nv_bfloat162*>(&hp);
    return packbf2(a - __bfloat162float(t.x), b - __bfloat162float(t.y));
}

// ===================== batched HMMA GEMM =========================================
// C[m,n] = scale*(sum_k A[m,k]*B[n,k] + bias[n]); A,B bf16 hi/lo, 3-term split.
#define BM 128
#define BN 128
#define BK 32
#define KST 40
#define STAGES 4
#define NCHUNKS (EDIM/BK)               // 24
#define ARR_BYTES (128*KST*2)
#define STAGE_BYTES (4*ARR_BYTES)
#define SM_AH 0
#define SM_AL (ARR_BYTES)
#define SM_BH (2*ARR_BYTES)
#define SM_BL (3*ARR_BYTES)
#define GEMM_SMEM (STAGES*STAGE_BYTES + 512)

struct GArg {
    const __nv_bfloat16 *Ah, *Al, *Bh, *Bl;
    const float* bias;
    float scale;
    float* outF;
    __nv_bfloat16 *outH, *outL;
};

__device__ __forceinline__ void load_chunk(
    uint32_t st, int chunk, int tid, int m0, int n0,
    const __nv_bfloat16* __restrict__ Ah, const __nv_bfloat16* __restrict__ Al,
    const __nv_bfloat16* __restrict__ Bh, const __nv_bfloat16* __restrict__ Bl)
{
    const int kc = chunk * BK;
#pragma unroll
    for (int i = 0; i < 2; i++) {
        int t = tid + i*256;
        int r = t >> 2;
        int seg = t & 3;
        uint32_t so = (uint32_t)(r*(KST*2) + seg*16);
        size_t goA = (size_t)(m0 + r)*EDIM + kc + seg*8;
        cp16g(st + SM_AH + so, Ah + goA);
        cp16g(st + SM_AL + so, Al + goA);
        size_t goB = (size_t)(n0 + r)*EDIM + kc + seg*8;
        cp16g(st + SM_BH + so, Bh + goB);
        cp16g(st + SM_BL + so, Bl + goB);
    }
    cp_commit();
}

__global__ __launch_bounds__(256, 1) void hmma_gemm_b3(GArg g0, GArg g1, GArg g2)
{
    const GArg g = (blockIdx.z == 0) ? g0 : ((blockIdx.z == 1) ? g1 : g2);
    extern __shared__ __align__(256) char smem[];
    const uint32_t sb = smem_u32(smem);
    const int tid  = threadIdx.x;
    const int lane = tid & 31;
    const int wid  = tid >> 5;
    const int warp_m = wid >> 2;
    const int warp_n = wid & 3;
    const int m0 = blockIdx.y * BM;
    const int n0 = blockIdx.x * BN;
    float* sbias = (float*)(smem + STAGES*STAGE_BYTES);
    if (tid < BN) sbias[tid] = g.bias ? g.bias[n0 + tid] : 0.f;

    float acc[4][4][4];
#pragma unroll
    for (int mi = 0; mi < 4; mi++)
#pragma unroll
        for (int ni = 0; ni < 4; ni++)
#pragma unroll
            for (int r = 0; r < 4; r++) acc[mi][ni][r] = 0.f;

#pragma unroll
    for (int s = 0; s < STAGES-1; s++)
        load_chunk(sb + s*STAGE_BYTES, s, tid, m0, n0, g.Ah, g.Al, g.Bh, g.Bl);

    const int a_row = warp_m*64 + (lane & 15);
    const int a_col = (lane >> 4) * 8;
    const int b_row = warp_n*32 + (lane & 7) + ((lane >> 4) << 3);
    const int b_col = ((lane >> 3) & 1) * 8;

    for (int c = 0; c < NCHUNKS; c++) {
        cp_wait<STAGES-2>();
        __syncthreads();
        if (c + STAGES-1 < NCHUNKS)
            load_chunk(sb + ((c + STAGES-1) % STAGES)*STAGE_BYTES, c + STAGES-1,
                       tid, m0, n0, g.Ah, g.Al, g.Bh, g.Bl);
        else
            cp_commit();

        const uint32_t stg = sb + (c % STAGES)*STAGE_BYTES;
#pragma unroll
        for (int kk = 0; kk < 2; kk++) {
            const uint32_t kof = kk*16;
            uint32_t ah[4][4], al[4][4];
#pragma unroll
            for (int mi = 0; mi < 4; mi++) {
                uint32_t ao = (uint32_t)((a_row + mi*16)*(KST*2) + (kof + a_col)*2);
                ldsm_x4(ah[mi], stg + SM_AH + ao);
                ldsm_x4(al[mi], stg + SM_AL + ao);
            }
            uint32_t bh[4][2], bl[4][2];
#pragma unroll
            for (int nn = 0; nn < 2; nn++) {
                uint32_t bo = (uint32_t)((b_row + nn*16)*(KST*2) + (kof + b_col)*2);
                uint32_t t[4];
                ldsm_x4(t, stg + SM_BH + bo);
                bh[nn*2][0] = t[0]; bh[nn*2][1] = t[1];
                bh[nn*2+1][0] = t[2]; bh[nn*2+1][1] = t[3];
                ldsm_x4(t, stg + SM_BL + bo);
                bl[nn*2][0] = t[0]; bl[nn*2][1] = t[1];
                bl[nn*2+1][0] = t[2]; bl[nn*2+1][1] = t[3];
            }
#pragma unroll
            for (int mi = 0; mi < 4; mi++)
#pragma unroll
                for (int ni = 0; ni < 4; ni++) {
                    mma16816(acc[mi][ni], ah[mi], bh[ni]);
                    mma16816(acc[mi][ni], ah[mi], bl[ni]);
                    mma16816(acc[mi][ni], al[mi], bh[ni]);
                }
        }
    }
    __syncthreads();

#pragma unroll
    for (int mi = 0; mi < 4; mi++) {
#pragma unroll
        for (int ni = 0; ni < 4; ni++) {
            int colL = warp_n*32 + ni*8 + (lane & 3)*2;
            int col  = n0 + colL;
            int row0 = m0 + warp_m*64 + mi*16 + (lane >> 2);
            float b0 = sbias[colL], b1 = sbias[colL+1];
            float v00 = g.scale*(acc[mi][ni][0] + b0);
            float v01 = g.scale*(acc[mi][ni][1] + b1);
            float v10 = g.scale*(acc[mi][ni][2] + b0);
            float v11 = g.scale*(acc[mi][ni][3] + b1);
            if (g.outF) {
                *(float2*)(g.outF + (size_t)row0*EDIM + col)     = make_float2(v00, v01);
                *(float2*)(g.outF + (size_t)(row0+8)*EDIM + col) = make_float2(v10, v11);
            }
            if (g.outH) {
                uint32_t h0 = packbf2(v00, v01);
                uint32_t h1 = packbf2(v10, v11);
                *(uint32_t*)(g.outH + (size_t)row0*EDIM + col)     = h0;
                *(uint32_t*)(g.outH + (size_t)(row0+8)*EDIM + col) = h1;
                *(uint32_t*)(g.outL + (size_t)row0*EDIM + col)     = packbf2_res(v00, v01, h0);
                *(uint32_t*)(g.outL + (size_t)(row0+8)*EDIM + col) = packbf2_res(v10, v11, h1);
            }
        }
    }
}

// ===================== prep kernels =============================================
// z-batched: build transposed folded-LoRA weights  WeffT[e*E+m] = Weff[m,e]
__global__ void build_wefft3_kernel(
    const float* W0, const float* A0, const float* B0, __nv_bfloat16* h0, __nv_bfloat16* l0,
    const float* W1, const float* A1, const float* B1, __nv_bfloat16* h1, __nv_bfloat16* l1,
    const float* W2, const float* A2, const float* B2, __nv_bfloat16* h2, __nv_bfloat16* l2)
{
    int z = blockIdx.z;
    const float* W = z==0 ? W0 : (z==1 ? W1 : W2);
    const float* A = z==0 ? A0 : (z==1 ? A1 : A2);
    const float* Bm = z==0 ? B0 : (z==1 ? B1 : B2);
    __nv_bfloat16* oh = z==0 ? h0 : (z==1 ? h1 : h2);
    __nv_bfloat16* ol = z==0 ? l0 : (z==1 ? l1 : l2);
    int idx = blockIdx.x * blockDim.x + threadIdx.x;
    if (idx >= EDIM*EDIM) return;
    int e = idx / EDIM;
    int m = idx - e*EDIM;
    float w = W[(size_t)m*EDIM + e] + 0.5f * (Bm[m*2+0]*A[e] + Bm[m*2+1]*A[EDIM + e]);
    __nv_bfloat16 h = __float2bfloat16(w);
    oh[idx] = h;
    ol[idx] = __float2bfloat16(w - __bfloat162float(h));
}

// z-batched plain hi/lo convert of 4 weights
__global__ void convert_w4_kernel(
    const float* w0, __nv_bfloat16* h0, __nv_bfloat16* l0,
    const float* w1, __nv_bfloat16* h1, __nv_bfloat16* l1,
    const float* w2, __nv_bfloat16* h2, __nv_bfloat16* l2,
    const float* w3, __nv_bfloat16* h3, __nv_bfloat16* l3)
{
    int z = blockIdx.z;
    const float* w = z==0 ? w0 : (z==1 ? w1 : (z==2 ? w2 : w3));
    __nv_bfloat16* oh = z==0 ? h0 : (z==1 ? h1 : (z==2 ? h2 : h3));
    __nv_bfloat16* ol = z==0 ? l0 : (z==1 ? l1 : (z==2 ? l2 : l3));
    int idx = blockIdx.x * blockDim.x + threadIdx.x;
    if (idx >= EDIM*EDIM) return;
    float v = w[idx];
    __nv_bfloat16 h = __float2bfloat16(v);
    oh[idx] = h;
    ol[idx] = __float2bfloat16(v - __bfloat162float(h));
}

__global__ void f32_to_hl_kernel(const float* __restrict__ in,
                                 __nv_bfloat16* __restrict__ oh,
                                 __nv_bfloat16* __restrict__ ol, int n)
{
    int idx = blockIdx.x * blockDim.x + threadIdx.x;
    if (idx >= n) return;
    float v = in[idx];
    __nv_bfloat16 h = __float2bfloat16(v);
    oh[idx] = h;
    ol[idx] = __float2bfloat16(v - __bfloat162float(h));
}

// combined bias: bc[z][o] = sum_m W[o,m]*b[m] + b[o]
__global__ void bcomb3_kernel(const float* Wq, const float* Wk, const float* Wv,
                              const float* bq, const float* bk, const float* bv,
                              float* bc)
{
    int o = blockIdx.x;
    int z = blockIdx.y;
    const float* W = z==0 ? Wq : (z==1 ? Wk : Wv);
    const float* b = z==0 ? bq : (z==1 ? bk : bv);
    int tid = threadIdx.x;
    float s = 0.f;
    for (int m = tid; m < EDIM; m += 128) s += W[(size_t)o*EDIM + m] * b[m];
#pragma unroll
    for (int off = 16; off > 0; off >>= 1) s += __shfl_xor_sync(0xffffffffu, s, off);
    __shared__ float red[4];
    if ((tid & 31) == 0) red[tid >> 5] = s;
    __syncthreads();
    if (tid == 0) bc[z*EDIM + o] = red[0] + red[1] + red[2] + red[3] + b[o];
}

// ===================== rel-pos bias table [NH][2048] ===========================
__global__ void relbias_kernel(const float* __restrict__ rel_embed, float* __restrict__ relb)
{
    int idx = blockIdx.x * blockDim.x + threadIdx.x;
    if (idx >= NH*2047) return;
    int h = idx / 2047;
    int d = idx - h*2047;
    int rel = d - 1023;
    const int nb = NB/2;
    const int max_exact = nb/2;
    int b = (rel > 0) ? nb : 0;
    int r = abs(rel);
    if (r < max_exact) {
        b += r;
    } else {
        float log_ratio = logf((float)r / (float)max_exact);
        float denom = logf(800.0f / (float)max_exact);
        int large = max_exact + (int)(log_ratio / denom * (float)(nb - max_exact));
        if (large > nb - 1) large = nb - 1;
        b += large;
    }
    relb[h*2048 + d] = rel_embed[(size_t)b*NH + h];
}

// ===================== gate ====================================================
__global__ void gate_kernel(const float* __restrict__ x,
                            const float* __restrict__ Wg,
                            const float* __restrict__ bg,
                            const float* __restrict__ gru,
                            float* __restrict__ gate)
{
    __shared__ float sWg[8*HD];
    __shared__ float sbg[8];
    int tid = threadIdx.x;
    for (int i = tid; i < 8*HD; i += blockDim.x) sWg[i] = Wg[i];
    if (tid < 8) sbg[tid] = bg[tid];
    __syncthreads();

    int idx = blockIdx.x * blockDim.x + tid;
    if (idx >= BSZ*NH*TQ) return;
    int t = idx % TQ;
    int h = (idx / TQ) % NH;
    int b = idx / (TQ*NH);

    const float* xp = x + ((size_t)b*TQ + t)*EDIM + h*HD;
    float gp[8];
#pragma unroll
    for (int e = 0; e < 8; e++) gp[e] = sbg[e];
#pragma unroll
    for (int d4 = 0; d4 < HD; d4 += 4) {
        float4 xv = *(const float4*)(xp + d4);
#pragma unroll
        for (int e = 0; e < 8; e++) {
            gp[e] = fmaf(xv.x, sWg[e*HD + d4+0], gp[e]);
            gp[e] = fmaf(xv.y, sWg[e*HD + d4+1], gp[e]);
            gp[e] = fmaf(xv.z, sWg[e*HD + d4+2], gp[e]);
            gp[e] = fmaf(xv.w, sWg[e*HD + d4+3], gp[e]);
        }
    }
    float s0 = gp[0]+gp[1]+gp[2]+gp[3];
    float s1 = gp[4]+gp[5]+gp[6]+gp[7];
    float ga = 1.0f / (1.0f + __expf(-s0));
    float gb = 1.0f / (1.0f + __expf(-s1));
    gate[idx] = ga * (gb * gru[h] - 1.0f) + 2.0f;
}

// ===================== HMMA flash attention (same engine as R4) =================
#define AQ 128
#define AKV 64
#define QSTR 72
#define A_QH 8192
#define A_QL (A_QH + AQ*QSTR*2)
#define A_KV (A_QL + AQ*QSTR*2)
#define KV_ARR (AKV*QSTR*2)
#define KV_STAGE (4*KV_ARR)
#define ATTN_SMEM (A_KV + 2*KV_STAGE)
#define NTILES (TQ/AKV)

__device__ __forceinline__ void attn_load_kv(
    uint32_t dst, size_t hb, int k0, int tid,
    const __nv_bfloat16* __restrict__ kh, const __nv_bfloat16* __restrict__ kl,
    const __nv_bfloat16* __restrict__ vh, const __nv_bfloat16* __restrict__ vl)
{
#pragma unroll
    for (int i = 0; i < 2; i++) {
        int t = tid + i*256;
        int r = t >> 3;
        int s = t & 7;
        uint32_t so = (uint32_t)(r*QSTR + s*8)*2;
        size_t go = hb + (size_t)(k0 + r)*EDIM + s*8;
        cp16g(dst + 0*KV_ARR + so, kh + go);
        cp16g(dst + 1*KV_ARR + so, kl + go);
        cp16g(dst + 2*KV_ARR + so, vh + go);
        cp16g(dst + 3*KV_ARR + so, vl + go);
    }
    cp_commit();
}

__global__ __launch_bounds__(256, 1) void attn_hmma_kernel(
    const __nv_bfloat16* __restrict__ qh, const __nv_bfloat16* __restrict__ ql,
    const __nv_bfloat16* __restrict__ kh, const __nv_bfloat16* __restrict__ kl,
    const __nv_bfloat16* __restrict__ vh, const __nv_bfloat16* __restrict__ vl,
    const float* __restrict__ gate, const float* __restrict__ relbg,
    __nv_bfloat16* __restrict__ ctxh, __nv_bfloat16* __restrict__ ctxl)
{
    extern __shared__ __align__(256) char asmem[];
    const uint32_t sb = smem_u32(asmem);
    float* relbs = (float*)asmem;
    const int tid  = threadIdx.x;
    const int lane = tid & 31;
    const int w    = tid >> 5;
    const int q0 = blockIdx.x * AQ;
    const int h  = blockIdx.y;
    const int b  = blockIdx.z;
    const size_t hb = (size_t)b*TQ*EDIM + h*HD;

    for (int i = tid; i < 2047; i += 256) relbs[i] = relbg[h*2048 + i];

#pragma unroll
    for (int i = 0; i < 4; i++) {
        int t = tid + i*256;
        int r = t >> 3;
        int s = t & 7;
        uint32_t so = (uint32_t)(r*QSTR + s*8)*2;
        size_t go = hb + (size_t)(q0 + r)*EDIM + s*8;
        cp16g(sb + A_QH + so, qh + go);
        cp16g(sb + A_QL + so, ql + go);
    }
    cp_commit();
    attn_load_kv(sb + A_KV, hb, 0, tid, kh, kl, vh, vl);

    const int lq  = lane >> 2;
    const int lc2 = (lane & 3) * 2;
    const int qg0 = q0 + w*16 + lq;
    const float grow0 = gate[((size_t)b*NH + h)*TQ + qg0];
    const float grow1 = gate[((size_t)b*NH + h)*TQ + qg0 + 8];

    float m0 = -1e30f, m1 = -1e30f, l0 = 0.f, l1 = 0.f;
    float o[8][4];
#pragma unroll
    for (int nf = 0; nf < 8; nf++)
#pragma unroll
        for (int e = 0; e < 4; e++) o[nf][e] = 0.f;

    uint32_t qhf[4][4], qlf[4][4];

    for (int t = 0; t < NTILES; t++) {
        if (t + 1 < NTILES)
            attn_load_kv(sb + A_KV + ((t+1)&1)*KV_STAGE, hb, (t+1)*AKV, tid, kh, kl, vh, vl);
        if (t + 1 < NTILES) cp_wait<1>(); else cp_wait<0>();
        __syncthreads();

        if (t == 0) {
#pragma unroll
            for (int kk = 0; kk < 4; kk++) {
                uint32_t ao = (uint32_t)(((w*16 + (lane & 15))*QSTR + (lane >> 4)*8 + kk*16)*2);
                ldsm_x4(qhf[kk], sb + A_QH + ao);
                ldsm_x4(qlf[kk], sb + A_QL + ao);
            }
        }
        const uint32_t kv = sb + A_KV + (t & 1)*KV_STAGE;

        float s[8][4];
#pragma unroll
        for (int nf = 0; nf < 8; nf++)
#pragma unroll
            for (int e = 0; e < 4; e++) s[nf][e] = 0.f;
#pragma unroll
        for (int kk = 0; kk < 4; kk++) {
#pragma unroll
            for (int nn = 0; nn < 4; nn++) {
                uint32_t bo = (uint32_t)(((nn*16 + (lane & 7) + ((lane >> 4) << 3))*QSTR
                                          + ((lane >> 3) & 1)*8 + kk*16)*2);
                uint32_t th[4], tl[4];
                ldsm_x4(th, kv + 0*KV_ARR + bo);
                ldsm_x4(tl, kv + 1*KV_ARR + bo);
                mma16816(s[2*nn],   qhf[kk], th);
                mma16816(s[2*nn],   qhf[kk], tl);
                mma16816(s[2*nn],   qlf[kk], th);
                mma16816(s[2*nn+1], qhf[kk], th+2);
                mma16816(s[2*nn+1], qhf[kk], tl+2);
                mma16816(s[2*nn+1], qlf[kk], th+2);
            }
        }

        const int k0 = t*AKV;
        float tm0 = -1e30f, tm1 = -1e30f;
#pragma unroll
        for (int nf = 0; nf < 8; nf++) {
            int d0 = (k0 + nf*8 + lc2) - qg0 + 1023;
            s[nf][0] = fmaf(grow0, relbs[d0],   s[nf][0]);
            s[nf][1] = fmaf(grow0, relbs[d0+1], s[nf][1]);
            s[nf][2] = fmaf(grow1, relbs[d0-8], s[nf][2]);
            s[nf][3] = fmaf(grow1, relbs[d0-7], s[nf][3]);
            tm0 = fmaxf(tm0, fmaxf(s[nf][0], s[nf][1]));
            tm1 = fmaxf(tm1, fmaxf(s[nf][2], s[nf][3]));
        }
#pragma unroll
        for (int off = 1; off < 4; off <<= 1) {
            tm0 = fmaxf(tm0, __shfl_xor_sync(0xffffffffu, tm0, off));
            tm1 = fmaxf(tm1, __shfl_xor_sync(0xffffffffu, tm1, off));
        }
        float mn0 = fmaxf(m0, tm0), mn1 = fmaxf(m1, tm1);
        float corr0 = __expf(m0 - mn0), corr1 = __expf(m1 - mn1);
        float ps0 = 0.f, ps1 = 0.f;
#pragma unroll
        for (int nf = 0; nf < 8; nf++) {
            s[nf][0] = __expf(s[nf][0] - mn0);
            s[nf][1] = __expf(s[nf][1] - mn0);
            s[nf][2] = __expf(s[nf][2] - mn1);
            s[nf][3] = __expf(s[nf][3] - mn1);
            ps0 += s[nf][0] + s[nf][1];
            ps1 += s[nf][2] + s[nf][3];
        }
#pragma unroll
        for (int off = 1; off < 4; off <<= 1) {
            ps0 += __shfl_xor_sync(0xffffffffu, ps0, off);
            ps1 += __shfl_xor_sync(0xffffffffu, ps1, off);
        }
        l0 = l0*corr0 + ps0;  m0 = mn0;
        l1 = l1*corr1 + ps1;  m1 = mn1;
#pragma unroll
        for (int nf = 0; nf < 8; nf++) {
            o[nf][0] *= corr0; o[nf][1] *= corr0;
            o[nf][2] *= corr1; o[nf][3] *= corr1;
        }

#pragma unroll
        for (int kk = 0; kk < 4; kk++) {
            uint32_t aph[4], apl[4];
            aph[0] = packbf2(s[2*kk][0],   s[2*kk][1]);
            aph[1] = packbf2(s[2*kk][2],   s[2*kk][3]);
            aph[2] = packbf2(s[2*kk+1][0], s[2*kk+1][1]);
            aph[3] = packbf2(s[2*kk+1][2], s[2*kk+1][3]);
            apl[0] = packbf2_res(s[2*kk][0],   s[2*kk][1],   aph[0]);
            apl[1] = packbf2_res(s[2*kk][2],   s[2*kk][3],   aph[1]);
            apl[2] = packbf2_res(s[2*kk+1][0], s[2*kk+1][1], aph[2]);
            apl[3] = packbf2_res(s[2*kk+1][2], s[2*kk+1][3], aph[3]);
#pragma unroll
            for (int nn = 0; nn < 4; nn++) {
                uint32_t vo = (uint32_t)(((kk*16 + (lane & 7) + (((lane >> 3) & 1) << 3))*QSTR
                                          + nn*16 + (lane >> 4)*8)*2);
                uint32_t th[4], tl[4];
                ldsm_x4_t(th, kv + 2*KV_ARR + vo);
                ldsm_x4_t(tl, kv + 3*KV_ARR + vo);
                mma16816(o[2*nn],   aph, th);
                mma16816(o[2*nn],   aph, tl);
                mma16816(o[2*nn],   apl, th);
                mma16816(o[2*nn+1], aph, th+2);
                mma16816(o[2*nn+1], aph, tl+2);
                mma16816(o[2*nn+1], apl, th+2);
            }
        }
        __syncthreads();
    }

    const float inv0 = 1.0f / l0;
    const float inv1 = 1.0f / l1;
#pragma unroll
    for (int nf = 0; nf < 8; nf++) {
        float v00 = o[nf][0]*inv0, v01 = o[nf][1]*inv0;
        float v10 = o[nf][2]*inv1, v11 = o[nf][3]*inv1;
        size_t r0 = hb + (size_t)qg0*EDIM + nf*8 + lc2;
        size_t r1 = r0 + (size_t)8*EDIM;
        uint32_t h0 = packbf2(v00, v01);
        uint32_t h1 = packbf2(v10, v11);
        *(uint32_t*)(ctxh + r0) = h0;
        *(uint32_t*)(ctxh + r1) = h1;
        *(uint32_t*)(ctxl + r0) = packbf2_res(v00, v01, h0);
        *(uint32_t*)(ctxl + r1) = packbf2_res(v10, v11, h1);
    }
}

// ===================== launch ===================================================
extern "C" void kernel_launch(void* const* d_in, const int* in_sizes, int n_in,
                              void* d_out, int out_size)
{
    const float* x   = (const float*)d_in[0];
    const float* Wq  = (const float*)d_in[1];
    const float* bq  = (const float*)d_in[2];
    const float* Wk  = (const float*)d_in[3];
    const float* bk  = (const float*)d_in[4];
    const float* Wv  = (const float*)d_in[5];
    const float* bv  = (const float*)d_in[6];
    const float* Aq  = (const float*)d_in[7];
    const float* Bq  = (const float*)d_in[8];
    const float* Ak  = (const float*)d_in[9];
    const float* Bk  = (const float*)d_in[10];
    const float* Av  = (const float*)d_in[11];
    const float* Bv  = (const float*)d_in[12];
    const float* Wo  = (const float*)d_in[13];
    const float* bo  = (const float*)d_in[14];
    const float* Wg  = (const float*)d_in[15];
    const float* bg  = (const float*)d_in[16];
    const float* gru = (const float*)d_in[17];
    const float* rel = (const float*)d_in[18];
    float* out = (float*)d_out;

    __nv_bfloat16 *xh,*xl,*q2h,*q2l,*k2h,*k2l,*v2h,*v2l,*ctxh,*ctxl;
    __nv_bfloat16 *wetqh,*wetql,*wetkh,*wetkl,*wetvh,*wetvl;
    __nv_bfloat16 *wqh,*wql,*wkh,*wkl,*wvh,*wvl,*woh,*wol;
    __nv_bfloat16 *wcqh,*wcql,*wckh,*wckl,*wcvh,*wcvl;
    float *gate, *relb, *bcomb;
    cudaGetSymbolAddress((void**)&xh, g_xh);     cudaGetSymbolAddress((void**)&xl, g_xl);
    cudaGetSymbolAddress((void**)&q2h, g_q2h);   cudaGetSymbolAddress((void**)&q2l, g_q2l);
    cudaGetSymbolAddress((void**)&k2h, g_k2h);   cudaGetSymbolAddress((void**)&k2l, g_k2l);
    cudaGetSymbolAddress((void**)&v2h, g_v2h);   cudaGetSymbolAddress((void**)&v2l, g_v2l);
    cudaGetSymbolAddress((void**)&ctxh, g_ctxh); cudaGetSymbolAddress((void**)&ctxl, g_ctxl);
    cudaGetSymbolAddress((void**)&wetqh, g_wetqh); cudaGetSymbolAddress((void**)&wetql, g_wetql);
    cudaGetSymbolAddress((void**)&wetkh, g_wetkh); cudaGetSymbolAddress((void**)&wetkl, g_wetkl);
    cudaGetSymbolAddress((void**)&wetvh, g_wetvh); cudaGetSymbolAddress((void**)&wetvl, g_wetvl);
    cudaGetSymbolAddress((void**)&wqh, g_wqh);   cudaGetSymbolAddress((void**)&wql, g_wql);
    cudaGetSymbolAddress((void**)&wkh, g_wkh);   cudaGetSymbolAddress((void**)&wkl, g_wkl);
    cudaGetSymbolAddress((void**)&wvh, g_wvh);   cudaGetSymbolAddress((void**)&wvl, g_wvl);
    cudaGetSymbolAddress((void**)&woh, g_woh);   cudaGetSymbolAddress((void**)&wol, g_wol);
    cudaGetSymbolAddress((void**)&wcqh, g_wcqh); cudaGetSymbolAddress((void**)&wcql, g_wcql);
    cudaGetSymbolAddress((void**)&wckh, g_wckh); cudaGetSymbolAddress((void**)&wckl, g_wckl);
    cudaGetSymbolAddress((void**)&wcvh, g_wcvh); cudaGetSymbolAddress((void**)&wcvl, g_wcvl);
    cudaGetSymbolAddress((void**)&gate, g_gate); cudaGetSymbolAddress((void**)&relb, g_relb);
    cudaGetSymbolAddress((void**)&bcomb, g_bcomb);

    cudaFuncSetAttribute(hmma_gemm_b3, cudaFuncAttributeMaxDynamicSharedMemorySize, GEMM_SMEM);
    cudaFuncSetAttribute(attn_hmma_kernel, cudaFuncAttributeMaxDynamicSharedMemorySize, ATTN_SMEM);

    const int nw = EDIM*EDIM;
    const int nx = MTOT*EDIM;
    const int wblocks = (nw+255)/256;

    // prep (3 launches instead of 8)
    convert_w4_kernel<<<dim3(wblocks,1,4), 256>>>(
        Wq, wqh, wql, Wk, wkh, wkl, Wv, wvh, wvl, Wo, woh, wol);
    build_wefft3_kernel<<<dim3(wblocks,1,3), 256>>>(
        Wq, Aq, Bq, wetqh, wetql,
        Wk, Ak, Bk, wetkh, wetkl,
        Wv, Av, Bv, wetvh, wetvl);
    f32_to_hl_kernel<<<(nx+255)/256, 256>>>(x, xh, xl, nx);

    // combined biases + gate + relbias
    bcomb3_kernel<<<dim3(EDIM,3), 128>>>(Wq, Wk, Wv, bq, bk, bv, bcomb);
    relbias_kernel<<<(NH*2047+255)/256, 256>>>(rel, relb);
    gate_kernel<<<(BSZ*NH*TQ+255)/256, 256>>>(x, Wg, bg, gru, gate);

    // weight-combine GEMMs: Wcomb = W @ Weff  (batched, 108 CTAs)
    {
        GArg cq{wqh, wql, wetqh, wetql, nullptr, 1.f, nullptr, wcqh, wcql};
        GArg ck{wkh, wkl, wetkh, wetkl, nullptr, 1.f, nullptr, wckh, wckl};
        GArg cv{wvh, wvl, wetvh, wetvl, nullptr, 1.f, nullptr, wcvh, wcvl};
        hmma_gemm_b3<<<dim3(EDIM/BN, EDIM/BM, 3), 256, GEMM_SMEM>>>(cq, ck, cv);
    }

    // fused QKV projections: q/k/v = scale*(x @ Wcomb^T + bcomb)
    {
        GArg aq{xh, xl, wcqh, wcql, bcomb + 0*EDIM, 0.125f, nullptr, q2h, q2l};
        GArg ak{xh, xl, wckh, wckl, bcomb + 1*EDIM, 1.f,    nullptr, k2h, k2l};
        GArg av{xh, xl, wcvh, wcvl, bcomb + 2*EDIM, 1.f,    nullptr, v2h, v2l};
        hmma_gemm_b3<<<dim3(EDIM/BN, MTOT/BM, 3), 256, GEMM_SMEM>>>(aq, ak, av);
    }

    attn_hmma_kernel<<<dim3(TQ/AQ, NH, BSZ), 256, ATTN_SMEM>>>(
        q2h, q2l, k2h, k2l, v2h, v2l, gate, relb, ctxh, ctxl);

    // output projection
    {
        GArg co{ctxh, ctxl, woh, wol, bo, 1.f, out, nullptr, nullptr};
        hmma_gemm_b3<<<dim3(EDIM/BN, MTOT/BM, 1), 256, GEMM_SMEM>>>(co, co, co);
    }
}